// round 5
// baseline (speedup 1.0000x reference)
#include <cuda_runtime.h>
#include <cuda_fp16.h>
#include <cstdint>
#include <cstddef>

#define D_TONES 88
#define DPAD    104
#define T_LEN   512
#define K2ST    256
#define BATCH   1024
#define TILE_T  64
#define NTILES  8

// ---------------- device scratch ----------------
__device__ __align__(16) __half g_wdh[K2ST * DPAD];     // fp16 weights [k][d]
__device__ float g_cst[K2ST];                           // sum_d log1mp
__device__ float g_a0[K2ST];                            // linear init w_init*x_init
__device__ float g_logB[(size_t)BATCH * TILE_T * K2ST]; // logB, then E in place (64MB, L2)
__device__ float g_msum[BATCH];                         // per-tile sum of row maxes
__device__ unsigned g_alpha_h[BATCH * 128];             // fp16x2 A-fragment carry (4 u32/lane)
__device__ float g_C[BATCH];
__device__ float g_part[BATCH];

// ---------------- helpers ----------------
__device__ __forceinline__ float warpMaxf(float v) {
#pragma unroll
    for (int s = 16; s > 0; s >>= 1) v = fmaxf(v, __shfl_xor_sync(0xffffffffu, v, s));
    return v;
}
__device__ __forceinline__ float warpSumf(float v) {
#pragma unroll
    for (int s = 16; s > 0; s >>= 1) v += __shfl_xor_sync(0xffffffffu, v, s);
    return v;
}
__device__ __forceinline__ unsigned smem_u32(const void* p) {
    return (unsigned)__cvta_generic_to_shared(p);
}
__device__ __forceinline__ unsigned packh2(float lo, float hi) {
    __half2 h = __floats2half2_rn(lo, hi);
    return *reinterpret_cast<unsigned*>(&h);
}
__device__ __forceinline__ unsigned movmT(unsigned s) {
    unsigned d;
    asm("movmatrix.sync.aligned.m8n8.trans.b16 %0,%1;" : "=r"(d) : "r"(s));
    return d;
}
__device__ __forceinline__ void mma16816(float d[4], const unsigned a[4],
                                         unsigned b0, unsigned b1) {
    asm volatile("mma.sync.aligned.m16n8k16.row.col.f32.f16.f16.f32 "
                 "{%0,%1,%2,%3},{%4,%5,%6,%7},{%8,%9},{%10,%11,%12,%13};"
                 : "=f"(d[0]), "=f"(d[1]), "=f"(d[2]), "=f"(d[3])
                 : "r"(a[0]), "r"(a[1]), "r"(a[2]), "r"(a[3]), "r"(b0), "r"(b1),
                   "f"(0.0f), "f"(0.0f), "f"(0.0f), "f"(0.0f));
}
// E gather in the orientation of the step's output fragment
__device__ __forceinline__ void loadE(float e[8], const float* __restrict__ r,
                                      bool tr, int bn, int bt) {
    if (!tr) {
        float2 p0 = *reinterpret_cast<const float2*>(r + bn);
        float2 p1 = *reinterpret_cast<const float2*>(r + bn + 128);
        float2 p2 = *reinterpret_cast<const float2*>(r + bn + 8);
        float2 p3 = *reinterpret_cast<const float2*>(r + bn + 136);
        e[0] = p0.x; e[1] = p0.y; e[2] = p1.x; e[3] = p1.y;
        e[4] = p2.x; e[5] = p2.y; e[6] = p3.x; e[7] = p3.y;
    } else {
        e[0] = r[bt];       e[1] = r[bt + 16];  e[2] = r[bt + 8];   e[3] = r[bt + 24];
        e[4] = r[bt + 128]; e[5] = r[bt + 144]; e[6] = r[bt + 136]; e[7] = r[bt + 152];
    }
}

// ---------------- K0: precompute ----------------
__global__ void k0_setup(const float* __restrict__ probs_y,
                         const float* __restrict__ w_init,
                         const float* __restrict__ x_init) {
    int k = threadIdx.x;  // 256
    float cs = 0.0f;
    for (int d = 0; d < DPAD; d++) {
        float w = 0.0f;
        if (d < D_TONES) {
            float py = probs_y[k * D_TONES + d];
            float l1 = log1pf(-py);
            w = logf(py) - l1;
            cs += l1;
        }
        g_wdh[k * DPAD + d] = __float2half_rn(w);
    }
    g_cst[k] = cs;
    g_a0[k] = w_init[k >> 4] * x_init[k & 15];
}

// ---------------- K1: emission GEMM via mma.sync (64t x 128k per block) ----------------
__global__ void __launch_bounds__(256) k1_emis(const float* __restrict__ seq,
                                               const int* __restrict__ lengths,
                                               const int* __restrict__ mb,
                                               int tile) {
    const int b   = blockIdx.x;
    const int nh2 = blockIdx.y;
    const int t0  = tile * TILE_T;
    const int row = __ldg(&mb[b]);
    const int len = __ldg(&lengths[row]);
    if (t0 >= len) return;

    __shared__ __align__(16) __half Asm[TILE_T][DPAD];
    __shared__ __align__(16) __half Bsm[128][DPAD];

    const int tid = threadIdx.x;
    const uint4* wp = reinterpret_cast<const uint4*>(g_wdh + (size_t)nh2 * 128 * DPAD);
    for (int idx = tid; idx < 128 * 13; idx += 256)
        reinterpret_cast<uint4*>(&Bsm[0][0])[idx] = __ldg(&wp[idx]);
    for (int idx = tid; idx < TILE_T * 2; idx += 256) {
        int r = idx >> 1, q = idx & 1;
        *reinterpret_cast<uint4*>(&Asm[r][88 + q * 8]) = make_uint4(0, 0, 0, 0);
    }
    const float4* sp = reinterpret_cast<const float4*>(seq + ((size_t)row * T_LEN + t0) * D_TONES);
    for (int idx = tid; idx < TILE_T * 22; idx += 256) {
        int r = idx / 22, c4 = idx % 22;
        float4 v = __ldg(&sp[(size_t)r * 22 + c4]);
        __half2 h0 = __floats2half2_rn(v.x, v.y);
        __half2 h1 = __floats2half2_rn(v.z, v.w);
        uint2 u;
        u.x = *reinterpret_cast<unsigned*>(&h0);
        u.y = *reinterpret_cast<unsigned*>(&h1);
        *reinterpret_cast<uint2*>(&Asm[r][c4 * 4]) = u;
    }
    __syncthreads();

    const int w = tid >> 5, lane = tid & 31;
    const int mt = w & 3;
    const int nh = (w >> 2) * 64;

    float c[8][4];
#pragma unroll
    for (int q = 0; q < 8; q++) { c[q][0] = c[q][1] = c[q][2] = c[q][3] = 0.0f; }

    const unsigned aBase = smem_u32(&Asm[mt * 16 + (lane & 15)][(lane >> 4) * 8]);
    const unsigned bBase = smem_u32(&Bsm[nh + ((lane >> 4) * 8) + (lane & 7)][((lane >> 3) & 1) * 8]);

#pragma unroll
    for (int ks = 0; ks < 6; ks++) {
        unsigned a0, a1, a2, a3;
        asm volatile("ldmatrix.sync.aligned.m8n8.x4.shared.b16 {%0,%1,%2,%3},[%4];"
                     : "=r"(a0), "=r"(a1), "=r"(a2), "=r"(a3) : "r"(aBase + ks * 32));
#pragma unroll
        for (int nt2 = 0; nt2 < 4; nt2++) {
            unsigned b0, b1, b2, b3;
            asm volatile("ldmatrix.sync.aligned.m8n8.x4.shared.b16 {%0,%1,%2,%3},[%4];"
                         : "=r"(b0), "=r"(b1), "=r"(b2), "=r"(b3)
                         : "r"(bBase + nt2 * (16 * DPAD * 2) + ks * 32));
            asm volatile("mma.sync.aligned.m16n8k16.row.col.f32.f16.f16.f32 "
                         "{%0,%1,%2,%3},{%4,%5,%6,%7},{%8,%9},{%0,%1,%2,%3};"
                         : "+f"(c[nt2 * 2][0]), "+f"(c[nt2 * 2][1]),
                           "+f"(c[nt2 * 2][2]), "+f"(c[nt2 * 2][3])
                         : "r"(a0), "r"(a1), "r"(a2), "r"(a3), "r"(b0), "r"(b1));
            asm volatile("mma.sync.aligned.m16n8k16.row.col.f32.f16.f16.f32 "
                         "{%0,%1,%2,%3},{%4,%5,%6,%7},{%8,%9},{%0,%1,%2,%3};"
                         : "+f"(c[nt2 * 2 + 1][0]), "+f"(c[nt2 * 2 + 1][1]),
                           "+f"(c[nt2 * 2 + 1][2]), "+f"(c[nt2 * 2 + 1][3])
                         : "r"(a0), "r"(a1), "r"(a2), "r"(a3), "r"(b2), "r"(b3));
        }
    }

    const int r0 = mt * 16 + (lane >> 2);
    const int cb = nh2 * 128 + nh;
    const int cl = 2 * (lane & 3);
    const size_t ro0 = ((size_t)b * TILE_T + r0) * K2ST;
    const size_t ro1 = ro0 + 8 * K2ST;
#pragma unroll
    for (int q = 0; q < 8; q++) {
        int colg = cb + q * 8 + cl;
        float2 cst2 = *reinterpret_cast<const float2*>(&g_cst[colg]);
        float2 o0 = make_float2(c[q][0] + cst2.x, c[q][1] + cst2.y);
        float2 o1 = make_float2(c[q][2] + cst2.x, c[q][3] + cst2.y);
        *reinterpret_cast<float2*>(&g_logB[ro0 + colg]) = o0;
        *reinterpret_cast<float2*>(&g_logB[ro1 + colg]) = o1;
    }
}

// ---------------- K1b: row max + in-place E=exp(logB-m) + tile sum of m ----------------
__global__ void __launch_bounds__(256) k1b_maxexp(const int* __restrict__ lengths,
                                                  const int* __restrict__ mb, int tile) {
    const int b = blockIdx.x;
    const int t0 = tile * TILE_T;
    const int len = __ldg(&lengths[__ldg(&mb[b])]);
    if (t0 >= len) return;
    __shared__ float m_sh[TILE_T];
    const int wid = threadIdx.x >> 5, lane = threadIdx.x & 31;
#pragma unroll
    for (int it = 0; it < 8; it++) {
        int t = wid * 8 + it;
        float* p = g_logB + ((size_t)b * TILE_T + t) * K2ST;
        float v[8];
#pragma unroll
        for (int q = 0; q < 8; q++) v[q] = p[lane + 32 * q];
        float mx = v[0];
#pragma unroll
        for (int q = 1; q < 8; q++) mx = fmaxf(mx, v[q]);
        mx = warpMaxf(mx);
#pragma unroll
        for (int q = 0; q < 8; q++) p[lane + 32 * q] = __expf(v[q] - mx);
        if (lane == 0) m_sh[t] = mx;
    }
    __syncthreads();
    if (threadIdx.x < 32) {
        int end = min(TILE_T, len - t0);
        float s = (lane < end ? m_sh[lane] : 0.0f) +
                  (32 + lane < end ? m_sh[32 + lane] : 0.0f);
        s = warpSumf(s);
        if (lane == 0) g_msum[b] = s;
    }
}

// ---------------- K2: tensor-core forward recursion, warp per batch element ----------------
// Z alternates orientation each step: even t -> A (normal), odd t -> A^T.
//   t odd : U = Z*X, V = (U^T)*W = A'^T    (E indexed transposed)
//   t even: U = Z*W, V = (U^T)*X = A''     (E indexed normal)
// Renorm every step in f32 keeps fp16 carry safe (E row max == 1).
__global__ void __launch_bounds__(256) k2_fwd(const float* __restrict__ probs_w,
                                              const float* __restrict__ probs_x,
                                              const int* __restrict__ lengths,
                                              const int* __restrict__ mb,
                                              int tile) {
    const int wid = threadIdx.x >> 5, lane = threadIdx.x & 31;
    const int b = blockIdx.x * 8 + wid;
    const int t0 = tile * TILE_T;
    const int len = __ldg(&lengths[__ldg(&mb[b])]);
    if (t0 >= len) return;

    const int g = lane >> 2, t4 = lane & 3;

    // constant B-fragments (fp16): reg0 = {M[2t4][n], M[2t4+1][n]}, reg1 = rows +8
    unsigned Xf00 = packh2(__ldg(&probs_x[(2 * t4) * 16 + g]),     __ldg(&probs_x[(2 * t4 + 1) * 16 + g]));
    unsigned Xf01 = packh2(__ldg(&probs_x[(2 * t4 + 8) * 16 + g]), __ldg(&probs_x[(2 * t4 + 9) * 16 + g]));
    unsigned Xf10 = packh2(__ldg(&probs_x[(2 * t4) * 16 + g + 8]),     __ldg(&probs_x[(2 * t4 + 1) * 16 + g + 8]));
    unsigned Xf11 = packh2(__ldg(&probs_x[(2 * t4 + 8) * 16 + g + 8]), __ldg(&probs_x[(2 * t4 + 9) * 16 + g + 8]));
    unsigned Wf00 = packh2(__ldg(&probs_w[(2 * t4) * 16 + g]),     __ldg(&probs_w[(2 * t4 + 1) * 16 + g]));
    unsigned Wf01 = packh2(__ldg(&probs_w[(2 * t4 + 8) * 16 + g]), __ldg(&probs_w[(2 * t4 + 9) * 16 + g]));
    unsigned Wf10 = packh2(__ldg(&probs_w[(2 * t4) * 16 + g + 8]),     __ldg(&probs_w[(2 * t4 + 1) * 16 + g + 8]));
    unsigned Wf11 = packh2(__ldg(&probs_w[(2 * t4 + 8) * 16 + g + 8]), __ldg(&probs_w[(2 * t4 + 9) * 16 + g + 8]));

    const float* lb = g_logB + (size_t)b * TILE_T * K2ST;
    const int bn = 16 * g + 2 * t4;   // normal-orientation E base
    const int bt = 32 * t4 + g;       // transposed-orientation E base

    unsigned Z[4];
    float C;
    int tl_start;
    if (tile == 0) {
        // t=0: Z = a0 * E0 (normal orientation)
        float2 a00 = *reinterpret_cast<const float2*>(g_a0 + bn);
        float2 a01 = *reinterpret_cast<const float2*>(g_a0 + bn + 128);
        float2 a02 = *reinterpret_cast<const float2*>(g_a0 + bn + 8);
        float2 a03 = *reinterpret_cast<const float2*>(g_a0 + bn + 136);
        float2 e00 = *reinterpret_cast<const float2*>(lb + bn);
        float2 e01 = *reinterpret_cast<const float2*>(lb + bn + 128);
        float2 e02 = *reinterpret_cast<const float2*>(lb + bn + 8);
        float2 e03 = *reinterpret_cast<const float2*>(lb + bn + 136);
        Z[0] = packh2(a00.x * e00.x, a00.y * e00.y);
        Z[1] = packh2(a01.x * e01.x, a01.y * e01.y);
        Z[2] = packh2(a02.x * e02.x, a02.y * e02.y);
        Z[3] = packh2(a03.x * e03.x, a03.y * e03.y);
        C = g_msum[b];
        tl_start = 1;
    } else {
        uint4 z4 = *reinterpret_cast<const uint4*>(&g_alpha_h[(size_t)b * 128 + lane * 4]);
        Z[0] = z4.x; Z[1] = z4.y; Z[2] = z4.z; Z[3] = z4.w;
        C = g_C[b] + g_msum[b];
        tl_start = 0;
    }

    const int tl_end = min(TILE_T, len - t0);
    float ecur[8];
    loadE(ecur, lb + (size_t)tl_start * K2ST, (tl_start & 1) != 0, bn, bt);

    for (int tl = tl_start; tl < tl_end; ++tl) {
        const bool tr = (tl & 1) != 0;     // t0 is even -> parity of t == parity of tl
        // prefetch next step's E (hides L2 latency behind the mma chain)
        float enx[8] = {0, 0, 0, 0, 0, 0, 0, 0};
        if (tl + 1 < tl_end) loadE(enx, lb + (size_t)(tl + 1) * K2ST, !tr, bn, bt);

        unsigned M00, M01, M10, M11, N00, N01, N10, N11;
        if (tr) { M00 = Xf00; M01 = Xf01; M10 = Xf10; M11 = Xf11;
                  N00 = Wf00; N01 = Wf01; N10 = Wf10; N11 = Wf11; }
        else    { M00 = Wf00; M01 = Wf01; M10 = Wf10; M11 = Wf11;
                  N00 = Xf00; N01 = Xf01; N10 = Xf10; N11 = Xf11; }

        float U0[4], U1[4];
        mma16816(U0, Z, M00, M01);
        mma16816(U1, Z, M10, M11);

        unsigned h0 = packh2(U0[0], U0[1]);
        unsigned h1 = packh2(U0[2], U0[3]);
        unsigned h2 = packh2(U1[0], U1[1]);
        unsigned h3 = packh2(U1[2], U1[3]);
        unsigned Zt[4];
        Zt[0] = movmT(h0); Zt[1] = movmT(h2); Zt[2] = movmT(h1); Zt[3] = movmT(h3);

        float V0[4], V1[4];
        mma16816(V0, Zt, N00, N01);
        mma16816(V1, Zt, N10, N11);

#pragma unroll
        for (int q = 0; q < 4; q++) { V0[q] *= ecur[q]; V1[q] *= ecur[4 + q]; }

        // per-step renorm (f32) -> fp16-safe carry
        float s = ((V0[0] + V0[1]) + (V0[2] + V0[3])) + ((V1[0] + V1[1]) + (V1[2] + V1[3]));
        s = warpSumf(s);
        float rcp = __fdividef(1.0f, s);
        C += __logf(s);

        Z[0] = packh2(V0[0] * rcp, V0[1] * rcp);
        Z[1] = packh2(V0[2] * rcp, V0[3] * rcp);
        Z[2] = packh2(V1[0] * rcp, V1[1] * rcp);
        Z[3] = packh2(V1[2] * rcp, V1[3] * rcp);

#pragma unroll
        for (int q = 0; q < 8; q++) ecur[q] = enx[q];
    }

    *reinterpret_cast<uint4*>(&g_alpha_h[(size_t)b * 128 + lane * 4]) =
        make_uint4(Z[0], Z[1], Z[2], Z[3]);
    if (lane == 0) g_C[b] = C;
}

// ---------------- K3: per-b loglik (sum of fp16 alpha fragments) ----------------
__global__ void k3_loglik() {   // grid=BATCH, 32 threads
    const int b = blockIdx.x, lane = threadIdx.x;
    uint4 z = *reinterpret_cast<const uint4*>(&g_alpha_h[(size_t)b * 128 + lane * 4]);
    float2 f0 = __half22float2(*reinterpret_cast<__half2*>(&z.x));
    float2 f1 = __half22float2(*reinterpret_cast<__half2*>(&z.y));
    float2 f2 = __half22float2(*reinterpret_cast<__half2*>(&z.z));
    float2 f3 = __half22float2(*reinterpret_cast<__half2*>(&z.w));
    float s = ((f0.x + f0.y) + (f1.x + f1.y)) + ((f2.x + f2.y) + (f3.x + f3.y));
    s = warpSumf(s);
    if (lane == 0) g_part[b] = g_C[b] + logf(s);
}

// ---------------- K4: final sum ----------------
__global__ void k4_sum(float* __restrict__ out) {
    __shared__ float red[8];
    const int lane = threadIdx.x & 31;
    const int w0 = threadIdx.x >> 5;
    float acc = 0.0f;
    for (int idx = threadIdx.x; idx < BATCH; idx += 256) acc += g_part[idx];
    acc = warpSumf(acc);
    if (lane == 0) red[w0] = acc;
    __syncthreads();
    if (threadIdx.x == 0) {
        float s = red[0];
#pragma unroll
        for (int w = 1; w < 8; w++) s += red[w];
        out[0] = s;
    }
}

// ---------------- launch ----------------
extern "C" void kernel_launch(void* const* d_in, const int* in_sizes, int n_in,
                              void* d_out, int out_size) {
    const float* seq     = (const float*)d_in[0];
    const float* probs_w = (const float*)d_in[1];
    const float* probs_x = (const float*)d_in[2];
    const float* w_init  = (const float*)d_in[3];
    const float* x_init  = (const float*)d_in[4];
    const float* probs_y = (const float*)d_in[5];
    const int*   lengths = (const int*)d_in[6];
    const int*   mb      = (const int*)d_in[7];
    float* out = (float*)d_out;

    k0_setup<<<1, 256>>>(probs_y, w_init, x_init);
    for (int tile = 0; tile < NTILES; tile++) {
        k1_emis<<<dim3(BATCH, 2), 256>>>(seq, lengths, mb, tile);
        k1b_maxexp<<<BATCH, 256>>>(lengths, mb, tile);
        k2_fwd<<<BATCH / 8, 256>>>(probs_w, probs_x, lengths, mb, tile);
    }
    k3_loglik<<<BATCH, 32>>>();
    k4_sum<<<1, 256>>>(out);
}

// round 6
// speedup vs baseline: 1.1583x; 1.1583x over previous
#include <cuda_runtime.h>
#include <cuda_fp16.h>
#include <cstdint>
#include <cstddef>

#define D_TONES 88
#define DPAD    104
#define T_LEN   512
#define K2ST    256
#define BATCH   1024
#define TILE_T  64
#define NTILES  8

// ---------------- device scratch ----------------
__device__ __align__(16) __half g_wdh[K2ST * DPAD];       // fp16 weights [k][d]
__device__ float g_cst[K2ST];                             // sum_d log1mp
__device__ float g_a0[K2ST];                              // linear init w_init*x_init
__device__ float g_logB[(size_t)BATCH * TILE_T * K2ST];   // f32 logB tile scratch (64MB, L2)
__device__ __align__(16) __half g_E[(size_t)BATCH * T_LEN * K2ST]; // fp16 E, all steps (256MB)
__device__ float g_msum[BATCH * NTILES];                  // per-(b,tile) masked sum of row maxes
__device__ float g_C[BATCH];
__device__ float g_part[BATCH];

// ---------------- helpers ----------------
__device__ __forceinline__ unsigned smem_u32(const void* p) {
    return (unsigned)__cvta_generic_to_shared(p);
}
__device__ __forceinline__ float warpMaxf(float v) {
#pragma unroll
    for (int s = 16; s > 0; s >>= 1) v = fmaxf(v, __shfl_xor_sync(0xffffffffu, v, s));
    return v;
}
__device__ __forceinline__ float warpSumf(float v) {
#pragma unroll
    for (int s = 16; s > 0; s >>= 1) v += __shfl_xor_sync(0xffffffffu, v, s);
    return v;
}
__device__ __forceinline__ unsigned packh2(float lo, float hi) {
    __half2 h = __floats2half2_rn(lo, hi);
    return *reinterpret_cast<unsigned*>(&h);
}
__device__ __forceinline__ __half2 u2h(unsigned u) { return *reinterpret_cast<__half2*>(&u); }
__device__ __forceinline__ unsigned h2u(__half2 h) { return *reinterpret_cast<unsigned*>(&h); }
__device__ __forceinline__ unsigned movmT(unsigned s) {
    unsigned d;
    asm("movmatrix.sync.aligned.m8n8.trans.b16 %0,%1;" : "=r"(d) : "r"(s));
    return d;
}
__device__ __forceinline__ void mma16816(float d[4], const unsigned a[4],
                                         unsigned b0, unsigned b1) {
    asm volatile("mma.sync.aligned.m16n8k16.row.col.f32.f16.f16.f32 "
                 "{%0,%1,%2,%3},{%4,%5,%6,%7},{%8,%9},{%10,%11,%12,%13};"
                 : "=f"(d[0]), "=f"(d[1]), "=f"(d[2]), "=f"(d[3])
                 : "r"(a[0]), "r"(a[1]), "r"(a[2]), "r"(a[3]), "r"(b0), "r"(b1),
                   "f"(0.0f), "f"(0.0f), "f"(0.0f), "f"(0.0f));
}
// E fragment (A-orientation): h2 pairs at row offsets {bn, bn+128, bn+8, bn+136}
__device__ __forceinline__ void loadE4(unsigned e[4], const __half* __restrict__ row, int bn) {
    e[0] = *reinterpret_cast<const unsigned*>(row + bn);
    e[1] = *reinterpret_cast<const unsigned*>(row + bn + 128);
    e[2] = *reinterpret_cast<const unsigned*>(row + bn + 8);
    e[3] = *reinterpret_cast<const unsigned*>(row + bn + 136);
}

// one recursion step: Z <- (W^T (Z X))^T-free normal-orientation update, fp16 carry
__device__ __forceinline__ void stepZ(unsigned Z[4], float& C, const unsigned E4[4],
                                      const unsigned Xf[4], const unsigned Wf[4]) {
    // --- off critical path: kappa from current Z ---
    float2 f0 = __half22float2(u2h(Z[0]));
    float2 f1 = __half22float2(u2h(Z[1]));
    float2 f2 = __half22float2(u2h(Z[2]));
    float2 f3 = __half22float2(u2h(Z[3]));
    float s = ((f0.x + f0.y) + (f1.x + f1.y)) + ((f2.x + f2.y) + (f3.x + f3.y));
    s = warpSumf(s);
    float kap = fminf(__fdividef(1024.0f, s), 60000.0f);
    __half kh = __float2half_rn(kap);
    C -= __logf(__half2float(kh));          // bookkeep the APPLIED (rounded) kappa
    __half2 k2h = __half2half2(kh);
    __half2 ek0 = __hmul2(u2h(E4[0]), k2h);
    __half2 ek1 = __hmul2(u2h(E4[1]), k2h);
    __half2 ek2 = __hmul2(u2h(E4[2]), k2h);
    __half2 ek3 = __hmul2(u2h(E4[3]), k2h);

    // --- critical chain: U = Z*X ; T = U^T * W ; Z' = T^T ⊙ Ekappa ---
    float U0[4], U1[4];
    mma16816(U0, Z, Xf[0], Xf[1]);
    mma16816(U1, Z, Xf[2], Xf[3]);
    unsigned Ut[4];
    Ut[0] = movmT(packh2(U0[0], U0[1]));
    Ut[1] = movmT(packh2(U1[0], U1[1]));
    Ut[2] = movmT(packh2(U0[2], U0[3]));
    Ut[3] = movmT(packh2(U1[2], U1[3]));
    float T0[4], T1[4];
    mma16816(T0, Ut, Wf[0], Wf[1]);
    mma16816(T1, Ut, Wf[2], Wf[3]);
    Z[0] = h2u(__hmul2(u2h(movmT(packh2(T0[0], T0[1]))), ek0));
    Z[1] = h2u(__hmul2(u2h(movmT(packh2(T1[0], T1[1]))), ek1));
    Z[2] = h2u(__hmul2(u2h(movmT(packh2(T0[2], T0[3]))), ek2));
    Z[3] = h2u(__hmul2(u2h(movmT(packh2(T1[2], T1[3]))), ek3));
}

// ---------------- K0: precompute ----------------
__global__ void k0_setup(const float* __restrict__ probs_y,
                         const float* __restrict__ w_init,
                         const float* __restrict__ x_init) {
    int k = threadIdx.x;  // 256
    float cs = 0.0f;
    for (int d = 0; d < DPAD; d++) {
        float w = 0.0f;
        if (d < D_TONES) {
            float py = probs_y[k * D_TONES + d];
            float l1 = log1pf(-py);
            w = logf(py) - l1;
            cs += l1;
        }
        g_wdh[k * DPAD + d] = __float2half_rn(w);
    }
    g_cst[k] = cs;
    g_a0[k] = w_init[k >> 4] * x_init[k & 15];
}

// ---------------- K1: emission GEMM via mma.sync (64t x 128k per block) ----------------
__global__ void __launch_bounds__(256) k1_emis(const float* __restrict__ seq,
                                               const int* __restrict__ lengths,
                                               const int* __restrict__ mb,
                                               int tile) {
    const int b   = blockIdx.x;
    const int nh2 = blockIdx.y;
    const int t0  = tile * TILE_T;
    const int row = __ldg(&mb[b]);
    const int len = __ldg(&lengths[row]);
    if (t0 >= len) return;

    __shared__ __align__(16) __half Asm[TILE_T][DPAD];
    __shared__ __align__(16) __half Bsm[128][DPAD];

    const int tid = threadIdx.x;
    const uint4* wp = reinterpret_cast<const uint4*>(g_wdh + (size_t)nh2 * 128 * DPAD);
    for (int idx = tid; idx < 128 * 13; idx += 256)
        reinterpret_cast<uint4*>(&Bsm[0][0])[idx] = __ldg(&wp[idx]);
    for (int idx = tid; idx < TILE_T * 2; idx += 256) {
        int r = idx >> 1, q = idx & 1;
        *reinterpret_cast<uint4*>(&Asm[r][88 + q * 8]) = make_uint4(0, 0, 0, 0);
    }
    const float4* sp = reinterpret_cast<const float4*>(seq + ((size_t)row * T_LEN + t0) * D_TONES);
    for (int idx = tid; idx < TILE_T * 22; idx += 256) {
        int r = idx / 22, c4 = idx % 22;
        float4 v = __ldg(&sp[(size_t)r * 22 + c4]);
        __half2 h0 = __floats2half2_rn(v.x, v.y);
        __half2 h1 = __floats2half2_rn(v.z, v.w);
        uint2 u;
        u.x = *reinterpret_cast<unsigned*>(&h0);
        u.y = *reinterpret_cast<unsigned*>(&h1);
        *reinterpret_cast<uint2*>(&Asm[r][c4 * 4]) = u;
    }
    __syncthreads();

    const int w = tid >> 5, lane = tid & 31;
    const int mt = w & 3;
    const int nh = (w >> 2) * 64;

    float c[8][4];
#pragma unroll
    for (int q = 0; q < 8; q++) { c[q][0] = c[q][1] = c[q][2] = c[q][3] = 0.0f; }

    const unsigned aBase = smem_u32(&Asm[mt * 16 + (lane & 15)][(lane >> 4) * 8]);
    const unsigned bBase = smem_u32(&Bsm[nh + ((lane >> 4) * 8) + (lane & 7)][((lane >> 3) & 1) * 8]);

#pragma unroll
    for (int ks = 0; ks < 6; ks++) {
        unsigned a0, a1, a2, a3;
        asm volatile("ldmatrix.sync.aligned.m8n8.x4.shared.b16 {%0,%1,%2,%3},[%4];"
                     : "=r"(a0), "=r"(a1), "=r"(a2), "=r"(a3) : "r"(aBase + ks * 32));
#pragma unroll
        for (int nt2 = 0; nt2 < 4; nt2++) {
            unsigned b0, b1, b2, b3;
            asm volatile("ldmatrix.sync.aligned.m8n8.x4.shared.b16 {%0,%1,%2,%3},[%4];"
                         : "=r"(b0), "=r"(b1), "=r"(b2), "=r"(b3)
                         : "r"(bBase + nt2 * (16 * DPAD * 2) + ks * 32));
            asm volatile("mma.sync.aligned.m16n8k16.row.col.f32.f16.f16.f32 "
                         "{%0,%1,%2,%3},{%4,%5,%6,%7},{%8,%9},{%0,%1,%2,%3};"
                         : "+f"(c[nt2 * 2][0]), "+f"(c[nt2 * 2][1]),
                           "+f"(c[nt2 * 2][2]), "+f"(c[nt2 * 2][3])
                         : "r"(a0), "r"(a1), "r"(a2), "r"(a3), "r"(b0), "r"(b1));
            asm volatile("mma.sync.aligned.m16n8k16.row.col.f32.f16.f16.f32 "
                         "{%0,%1,%2,%3},{%4,%5,%6,%7},{%8,%9},{%0,%1,%2,%3};"
                         : "+f"(c[nt2 * 2 + 1][0]), "+f"(c[nt2 * 2 + 1][1]),
                           "+f"(c[nt2 * 2 + 1][2]), "+f"(c[nt2 * 2 + 1][3])
                         : "r"(a0), "r"(a1), "r"(a2), "r"(a3), "r"(b2), "r"(b3));
        }
    }

    const int r0 = mt * 16 + (lane >> 2);
    const int cb = nh2 * 128 + nh;
    const int cl = 2 * (lane & 3);
    const size_t ro0 = ((size_t)b * TILE_T + r0) * K2ST;
    const size_t ro1 = ro0 + 8 * K2ST;
#pragma unroll
    for (int q = 0; q < 8; q++) {
        int colg = cb + q * 8 + cl;
        float2 cst2 = *reinterpret_cast<const float2*>(&g_cst[colg]);
        float2 o0 = make_float2(c[q][0] + cst2.x, c[q][1] + cst2.y);
        float2 o1 = make_float2(c[q][2] + cst2.x, c[q][3] + cst2.y);
        *reinterpret_cast<float2*>(&g_logB[ro0 + colg]) = o0;
        *reinterpret_cast<float2*>(&g_logB[ro1 + colg]) = o1;
    }
}

// ---------------- K1b: row max + fp16 E store + per-tile masked m sum ----------------
__global__ void __launch_bounds__(256) k1b_maxexp(const int* __restrict__ lengths,
                                                  const int* __restrict__ mb, int tile) {
    const int b = blockIdx.x;
    const int t0 = tile * TILE_T;
    const int len = __ldg(&lengths[__ldg(&mb[b])]);
    if (t0 >= len) return;
    __shared__ float ms_sh[8];
    const int wid = threadIdx.x >> 5, lane = threadIdx.x & 31;
    float msl = 0.0f;
#pragma unroll
    for (int it = 0; it < 8; it++) {
        int tl = wid * 8 + it;
        const float4* p = reinterpret_cast<const float4*>(
            g_logB + ((size_t)b * TILE_T + tl) * K2ST);
        float4 v0 = p[lane];
        float4 v1 = p[lane + 32];
        float mx = fmaxf(fmaxf(fmaxf(v0.x, v0.y), fmaxf(v0.z, v0.w)),
                         fmaxf(fmaxf(v1.x, v1.y), fmaxf(v1.z, v1.w)));
        mx = warpMaxf(mx);
        uint2 u0, u1;
        u0.x = packh2(__expf(v0.x - mx), __expf(v0.y - mx));
        u0.y = packh2(__expf(v0.z - mx), __expf(v0.w - mx));
        u1.x = packh2(__expf(v1.x - mx), __expf(v1.y - mx));
        u1.y = packh2(__expf(v1.z - mx), __expf(v1.w - mx));
        uint2* eo = reinterpret_cast<uint2*>(g_E + ((size_t)b * T_LEN + t0 + tl) * K2ST);
        eo[lane] = u0;
        eo[lane + 32] = u1;
        if (t0 + tl < len) msl += mx;
    }
    if (lane == 0) ms_sh[wid] = msl;
    __syncthreads();
    if (threadIdx.x == 0) {
        float s = ms_sh[0];
#pragma unroll
        for (int q = 1; q < 8; q++) s += ms_sh[q];
        g_msum[b * NTILES + tile] = s;
    }
}

// ---------------- K2: tensor-core forward recursion, ONE launch, warp per b ----------------
__global__ void __launch_bounds__(256) k2_fwd(const float* __restrict__ probs_w,
                                              const float* __restrict__ probs_x,
                                              const int* __restrict__ lengths,
                                              const int* __restrict__ mb) {
    const int wid = threadIdx.x >> 5, lane = threadIdx.x & 31;
    const int b = blockIdx.x * 8 + wid;
    const int len = __ldg(&lengths[__ldg(&mb[b])]);

    const int g = lane >> 2, t4 = lane & 3;
    unsigned Xf[4], Wf[4];
    Xf[0] = packh2(__ldg(&probs_x[(2 * t4) * 16 + g]),     __ldg(&probs_x[(2 * t4 + 1) * 16 + g]));
    Xf[1] = packh2(__ldg(&probs_x[(2 * t4 + 8) * 16 + g]), __ldg(&probs_x[(2 * t4 + 9) * 16 + g]));
    Xf[2] = packh2(__ldg(&probs_x[(2 * t4) * 16 + g + 8]),     __ldg(&probs_x[(2 * t4 + 1) * 16 + g + 8]));
    Xf[3] = packh2(__ldg(&probs_x[(2 * t4 + 8) * 16 + g + 8]), __ldg(&probs_x[(2 * t4 + 9) * 16 + g + 8]));
    Wf[0] = packh2(__ldg(&probs_w[(2 * t4) * 16 + g]),     __ldg(&probs_w[(2 * t4 + 1) * 16 + g]));
    Wf[1] = packh2(__ldg(&probs_w[(2 * t4 + 8) * 16 + g]), __ldg(&probs_w[(2 * t4 + 9) * 16 + g]));
    Wf[2] = packh2(__ldg(&probs_w[(2 * t4) * 16 + g + 8]),     __ldg(&probs_w[(2 * t4 + 1) * 16 + g + 8]));
    Wf[3] = packh2(__ldg(&probs_w[(2 * t4 + 8) * 16 + g + 8]), __ldg(&probs_w[(2 * t4 + 9) * 16 + g + 8]));

    const __half* eb = g_E + (size_t)b * T_LEN * K2ST;
    const int bn = 16 * g + 2 * t4;

    // init t=0: Z = a0 ⊙ E0, normalized to sum 1024 in f32
    unsigned Z[4];
    float C;
    {
        float2 a0p = *reinterpret_cast<const float2*>(g_a0 + bn);
        float2 a1p = *reinterpret_cast<const float2*>(g_a0 + bn + 128);
        float2 a2p = *reinterpret_cast<const float2*>(g_a0 + bn + 8);
        float2 a3p = *reinterpret_cast<const float2*>(g_a0 + bn + 136);
        float2 e0p = __half22float2(*reinterpret_cast<const __half2*>(eb + bn));
        float2 e1p = __half22float2(*reinterpret_cast<const __half2*>(eb + bn + 128));
        float2 e2p = __half22float2(*reinterpret_cast<const __half2*>(eb + bn + 8));
        float2 e3p = __half22float2(*reinterpret_cast<const __half2*>(eb + bn + 136));
        float p0x = a0p.x * e0p.x, p0y = a0p.y * e0p.y;
        float p1x = a1p.x * e1p.x, p1y = a1p.y * e1p.y;
        float p2x = a2p.x * e2p.x, p2y = a2p.y * e2p.y;
        float p3x = a3p.x * e3p.x, p3y = a3p.y * e3p.y;
        float s0 = ((p0x + p0y) + (p1x + p1y)) + ((p2x + p2y) + (p3x + p3y));
        s0 = warpSumf(s0);
        float kap0 = __fdividef(1024.0f, s0);
        C = -__logf(kap0);
        Z[0] = packh2(p0x * kap0, p0y * kap0);
        Z[1] = packh2(p1x * kap0, p1y * kap0);
        Z[2] = packh2(p2x * kap0, p2y * kap0);
        Z[3] = packh2(p3x * kap0, p3y * kap0);
    }

    // prefetch ring depth 4
    unsigned EA[4][4];
#pragma unroll
    for (int u = 0; u < 4; u++) {
        int tp = min(1 + u, len - 1);
        loadE4(EA[u], eb + (size_t)tp * K2ST, bn);
    }
    int t = 1;
    for (; t + 3 < len; t += 4) {
        stepZ(Z, C, EA[0], Xf, Wf);
        loadE4(EA[0], eb + (size_t)min(t + 4, len - 1) * K2ST, bn);
        stepZ(Z, C, EA[1], Xf, Wf);
        loadE4(EA[1], eb + (size_t)min(t + 5, len - 1) * K2ST, bn);
        stepZ(Z, C, EA[2], Xf, Wf);
        loadE4(EA[2], eb + (size_t)min(t + 6, len - 1) * K2ST, bn);
        stepZ(Z, C, EA[3], Xf, Wf);
        loadE4(EA[3], eb + (size_t)min(t + 7, len - 1) * K2ST, bn);
    }
    for (; t < len; t++) {
        unsigned E4[4];
        loadE4(E4, eb + (size_t)t * K2ST, bn);
        stepZ(Z, C, E4, Xf, Wf);
    }

    // finalize: C += log(sum Z)
    float2 f0 = __half22float2(u2h(Z[0]));
    float2 f1 = __half22float2(u2h(Z[1]));
    float2 f2 = __half22float2(u2h(Z[2]));
    float2 f3 = __half22float2(u2h(Z[3]));
    float s = ((f0.x + f0.y) + (f1.x + f1.y)) + ((f2.x + f2.y) + (f3.x + f3.y));
    s = warpSumf(s);
    C += __logf(s);
    if (lane == 0) g_C[b] = C;
}

// ---------------- K3: per-b loglik = C + masked sum of tile m-sums ----------------
__global__ void k3_loglik(const int* __restrict__ lengths, const int* __restrict__ mb) {
    const int b = blockIdx.x * 256 + threadIdx.x;
    const int len = __ldg(&lengths[__ldg(&mb[b])]);
    const int nt = min((len + TILE_T - 1) / TILE_T, NTILES);
    float ms = 0.0f;
    for (int q = 0; q < nt; q++) ms += g_msum[b * NTILES + q];
    g_part[b] = g_C[b] + ms;
}

// ---------------- K4: final sum ----------------
__global__ void k4_sum(float* __restrict__ out) {
    __shared__ float red[8];
    const int lane = threadIdx.x & 31;
    const int w0 = threadIdx.x >> 5;
    float acc = 0.0f;
    for (int idx = threadIdx.x; idx < BATCH; idx += 256) acc += g_part[idx];
    acc = warpSumf(acc);
    if (lane == 0) red[w0] = acc;
    __syncthreads();
    if (threadIdx.x == 0) {
        float s = red[0];
#pragma unroll
        for (int w = 1; w < 8; w++) s += red[w];
        out[0] = s;
    }
}

// ---------------- launch ----------------
extern "C" void kernel_launch(void* const* d_in, const int* in_sizes, int n_in,
                              void* d_out, int out_size) {
    const float* seq     = (const float*)d_in[0];
    const float* probs_w = (const float*)d_in[1];
    const float* probs_x = (const float*)d_in[2];
    const float* w_init  = (const float*)d_in[3];
    const float* x_init  = (const float*)d_in[4];
    const float* probs_y = (const float*)d_in[5];
    const int*   lengths = (const int*)d_in[6];
    const int*   mb      = (const int*)d_in[7];
    float* out = (float*)d_out;

    k0_setup<<<1, 256>>>(probs_y, w_init, x_init);
    for (int tile = 0; tile < NTILES; tile++) {
        k1_emis<<<dim3(BATCH, 2), 256>>>(seq, lengths, mb, tile);
        k1b_maxexp<<<BATCH, 256>>>(lengths, mb, tile);
    }
    k2_fwd<<<BATCH / 8, 256>>>(probs_w, probs_x, lengths, mb);
    k3_loglik<<<BATCH / 256, 256>>>(lengths, mb);
    k4_sum<<<1, 256>>>(out);
}

// round 7
// speedup vs baseline: 1.5624x; 1.3489x over previous
#include <cuda_runtime.h>
#include <cuda_fp16.h>
#include <cstdint>
#include <cstddef>

#define D_TONES 88
#define DPAD    104
#define T_LEN   512
#define K2ST    256
#define BATCH   1024
#define TILE_T  64
#define NTILES  8

// ---------------- device scratch ----------------
__device__ __align__(16) __half g_wdh[K2ST * DPAD];       // fp16 weights [k][d]
__device__ float g_cst[K2ST];                             // sum_d log1mp
__device__ float g_a0[K2ST];                              // linear init w_init*x_init
__device__ __align__(16) __half g_E[(size_t)BATCH * T_LEN * K2ST]; // fp16 E (256MB)
__device__ float g_msum[BATCH];                           // per-b masked sum of row maxes
__device__ float g_C[BATCH];
__device__ float g_part[BATCH];

// smem layout offsets for k1f (bytes)
#define SM_A    0                       // 64 x DPAD half  = 13312
#define SM_B    13312                   // 256 x DPAD half = 53248
#define SM_CST  66560                   // 256 f32 = 1024
#define SM_RMX  67584                   // 4 x 2 x 16 f32 = 512
#define SM_WSUM 68096                   // 4 f32
#define SM_TOT  68128

// ---------------- helpers ----------------
__device__ __forceinline__ unsigned smem_u32(const void* p) {
    return (unsigned)__cvta_generic_to_shared(p);
}
__device__ __forceinline__ float warpSumf(float v) {
#pragma unroll
    for (int s = 16; s > 0; s >>= 1) v += __shfl_xor_sync(0xffffffffu, v, s);
    return v;
}
__device__ __forceinline__ unsigned packh2(float lo, float hi) {
    __half2 h = __floats2half2_rn(lo, hi);
    return *reinterpret_cast<unsigned*>(&h);
}
__device__ __forceinline__ __half2 u2h(unsigned u) { return *reinterpret_cast<__half2*>(&u); }
__device__ __forceinline__ unsigned h2u(__half2 h) { return *reinterpret_cast<unsigned*>(&h); }
__device__ __forceinline__ unsigned movmT(unsigned s) {
    unsigned d;
    asm("movmatrix.sync.aligned.m8n8.trans.b16 %0,%1;" : "=r"(d) : "r"(s));
    return d;
}
__device__ __forceinline__ void mma16816(float d[4], const unsigned a[4],
                                         unsigned b0, unsigned b1) {
    asm volatile("mma.sync.aligned.m16n8k16.row.col.f32.f16.f16.f32 "
                 "{%0,%1,%2,%3},{%4,%5,%6,%7},{%8,%9},{%10,%11,%12,%13};"
                 : "=f"(d[0]), "=f"(d[1]), "=f"(d[2]), "=f"(d[3])
                 : "r"(a[0]), "r"(a[1]), "r"(a[2]), "r"(a[3]), "r"(b0), "r"(b1),
                   "f"(0.0f), "f"(0.0f), "f"(0.0f), "f"(0.0f));
}
__device__ __forceinline__ void loadE4(unsigned e[4], const __half* __restrict__ row, int bn) {
    e[0] = *reinterpret_cast<const unsigned*>(row + bn);
    e[1] = *reinterpret_cast<const unsigned*>(row + bn + 128);
    e[2] = *reinterpret_cast<const unsigned*>(row + bn + 8);
    e[3] = *reinterpret_cast<const unsigned*>(row + bn + 136);
}

// one recursion step (validated R6): fp16 carry, deferred renorm folded into E
__device__ __forceinline__ void stepZ(unsigned Z[4], float& C, const unsigned E4[4],
                                      const unsigned Xf[4], const unsigned Wf[4]) {
    float2 f0 = __half22float2(u2h(Z[0]));
    float2 f1 = __half22float2(u2h(Z[1]));
    float2 f2 = __half22float2(u2h(Z[2]));
    float2 f3 = __half22float2(u2h(Z[3]));
    float s = ((f0.x + f0.y) + (f1.x + f1.y)) + ((f2.x + f2.y) + (f3.x + f3.y));
    s = warpSumf(s);
    float kap = fminf(__fdividef(1024.0f, s), 60000.0f);
    __half kh = __float2half_rn(kap);
    C -= __logf(__half2float(kh));
    __half2 k2h = __half2half2(kh);
    __half2 ek0 = __hmul2(u2h(E4[0]), k2h);
    __half2 ek1 = __hmul2(u2h(E4[1]), k2h);
    __half2 ek2 = __hmul2(u2h(E4[2]), k2h);
    __half2 ek3 = __hmul2(u2h(E4[3]), k2h);

    float U0[4], U1[4];
    mma16816(U0, Z, Xf[0], Xf[1]);
    mma16816(U1, Z, Xf[2], Xf[3]);
    unsigned Ut[4];
    Ut[0] = movmT(packh2(U0[0], U0[1]));
    Ut[1] = movmT(packh2(U1[0], U1[1]));
    Ut[2] = movmT(packh2(U0[2], U0[3]));
    Ut[3] = movmT(packh2(U1[2], U1[3]));
    float T0[4], T1[4];
    mma16816(T0, Ut, Wf[0], Wf[1]);
    mma16816(T1, Ut, Wf[2], Wf[3]);
    Z[0] = h2u(__hmul2(u2h(movmT(packh2(T0[0], T0[1]))), ek0));
    Z[1] = h2u(__hmul2(u2h(movmT(packh2(T1[0], T1[1]))), ek1));
    Z[2] = h2u(__hmul2(u2h(movmT(packh2(T0[2], T0[3]))), ek2));
    Z[3] = h2u(__hmul2(u2h(movmT(packh2(T1[2], T1[3]))), ek3));
}

// ---------------- K0: precompute ----------------
__global__ void k0_setup(const float* __restrict__ probs_y,
                         const float* __restrict__ w_init,
                         const float* __restrict__ x_init) {
    int k = threadIdx.x;  // 256
    float cs = 0.0f;
    for (int d = 0; d < DPAD; d++) {
        float w = 0.0f;
        if (d < D_TONES) {
            float py = probs_y[k * D_TONES + d];
            float l1 = log1pf(-py);
            w = logf(py) - l1;
            cs += l1;
        }
        g_wdh[k * DPAD + d] = __float2half_rn(w);
    }
    g_cst[k] = cs;
    g_a0[k] = w_init[k >> 4] * x_init[k & 15];
}

// ---------------- K1f: fused emission GEMM + rowmax + exp + fp16 E, persistent per b ----
__global__ void __launch_bounds__(256) k1f_emis(const float* __restrict__ seq,
                                                const int* __restrict__ lengths,
                                                const int* __restrict__ mb) {
    extern __shared__ __align__(16) unsigned char sraw[];
    __half (*Asm)[DPAD] = reinterpret_cast<__half(*)[DPAD]>(sraw + SM_A);
    __half (*Bsm)[DPAD] = reinterpret_cast<__half(*)[DPAD]>(sraw + SM_B);
    float* csm = reinterpret_cast<float*>(sraw + SM_CST);
    float (*rmx)[2][16] = reinterpret_cast<float(*)[2][16]>(sraw + SM_RMX);
    float* wsum = reinterpret_cast<float*>(sraw + SM_WSUM);

    const int b = blockIdx.x;
    const int tid = threadIdx.x;
    const int row = __ldg(&mb[b]);
    const int len = __ldg(&lengths[row]);

    // load all 256-state weights + cst into smem ONCE
    {
        const uint4* wp = reinterpret_cast<const uint4*>(g_wdh);
        uint4* bq = reinterpret_cast<uint4*>(&Bsm[0][0]);
        for (int idx = tid; idx < 256 * 13; idx += 256) bq[idx] = __ldg(&wp[idx]);
        csm[tid] = g_cst[tid];
        // zero A pad cols 88..103 once
        for (int r = tid; r < TILE_T; r += 256) {
            *reinterpret_cast<uint4*>(&Asm[r][88]) = make_uint4(0, 0, 0, 0);
            *reinterpret_cast<uint4*>(&Asm[r][96]) = make_uint4(0, 0, 0, 0);
        }
    }

    const int w = tid >> 5, lane = tid & 31;
    const int rg = w & 3;           // row group (16 rows)
    const int g  = w >> 2;          // col group (64-col slabs at g*64 and g*64+128)
    const int l4 = lane & 3, lr = lane >> 2;

    const unsigned aBase = smem_u32(&Asm[rg * 16 + (lane & 15)][(lane >> 4) * 8]);
    const unsigned bBase = smem_u32(&Bsm[g * 64 + ((lane >> 4) * 8) + (lane & 7)][((lane >> 3) & 1) * 8]);

    float msl = 0.0f;

    for (int tile = 0; tile < NTILES; tile++) {
        const int t0 = tile * TILE_T;
        if (t0 >= len) break;
        __syncthreads();   // prior rowmax reads + (iter 0) B/cst/pad init complete

        // fill A tile (f32 -> fp16)
        const float4* sp = reinterpret_cast<const float4*>(
            seq + ((size_t)row * T_LEN + t0) * D_TONES);
        for (int idx = tid; idx < TILE_T * 22; idx += 256) {
            int r = idx / 22, c4 = idx % 22;
            float4 v = __ldg(&sp[(size_t)r * 22 + c4]);
            __half2 h0 = __floats2half2_rn(v.x, v.y);
            __half2 h1 = __floats2half2_rn(v.z, v.w);
            uint2 u;
            u.x = *reinterpret_cast<unsigned*>(&h0);
            u.y = *reinterpret_cast<unsigned*>(&h1);
            *reinterpret_cast<uint2*>(&Asm[r][c4 * 4]) = u;
        }
        __syncthreads();

        float c[2][8][4];
#pragma unroll
        for (int cg = 0; cg < 2; cg++)
#pragma unroll
            for (int q = 0; q < 8; q++) {
                c[cg][q][0] = 0.0f; c[cg][q][1] = 0.0f;
                c[cg][q][2] = 0.0f; c[cg][q][3] = 0.0f;
            }

#pragma unroll
        for (int ks = 0; ks < 6; ks++) {
            unsigned a0, a1, a2, a3;
            asm volatile("ldmatrix.sync.aligned.m8n8.x4.shared.b16 {%0,%1,%2,%3},[%4];"
                         : "=r"(a0), "=r"(a1), "=r"(a2), "=r"(a3) : "r"(aBase + ks * 32));
#pragma unroll
            for (int cg = 0; cg < 2; cg++) {
#pragma unroll
                for (int q16 = 0; q16 < 4; q16++) {
                    unsigned b0, b1, b2, b3;
                    asm volatile("ldmatrix.sync.aligned.m8n8.x4.shared.b16 {%0,%1,%2,%3},[%4];"
                                 : "=r"(b0), "=r"(b1), "=r"(b2), "=r"(b3)
                                 : "r"(bBase + (cg * 128 + q16 * 16) * (DPAD * 2) + ks * 32));
                    float* cl0 = c[cg][q16 * 2];
                    float* cl1 = c[cg][q16 * 2 + 1];
                    asm volatile("mma.sync.aligned.m16n8k16.row.col.f32.f16.f16.f32 "
                                 "{%0,%1,%2,%3},{%4,%5,%6,%7},{%8,%9},{%0,%1,%2,%3};"
                                 : "+f"(cl0[0]), "+f"(cl0[1]), "+f"(cl0[2]), "+f"(cl0[3])
                                 : "r"(a0), "r"(a1), "r"(a2), "r"(a3), "r"(b0), "r"(b1));
                    asm volatile("mma.sync.aligned.m16n8k16.row.col.f32.f16.f16.f32 "
                                 "{%0,%1,%2,%3},{%4,%5,%6,%7},{%8,%9},{%0,%1,%2,%3};"
                                 : "+f"(cl1[0]), "+f"(cl1[1]), "+f"(cl1[2]), "+f"(cl1[3])
                                 : "r"(a0), "r"(a1), "r"(a2), "r"(a3), "r"(b2), "r"(b3));
                }
            }
        }

        // epilogue: +cst, row max (quad + cross-warp), exp, fp16 store
        float vmax0 = -3.4e38f, vmax1 = -3.4e38f;
#pragma unroll
        for (int cg = 0; cg < 2; cg++)
#pragma unroll
            for (int q = 0; q < 8; q++) {
                int col = g * 64 + cg * 128 + q * 8 + l4 * 2;
                float2 cst2 = *reinterpret_cast<const float2*>(&csm[col]);
                c[cg][q][0] += cst2.x; c[cg][q][1] += cst2.y;
                c[cg][q][2] += cst2.x; c[cg][q][3] += cst2.y;
                vmax0 = fmaxf(vmax0, fmaxf(c[cg][q][0], c[cg][q][1]));
                vmax1 = fmaxf(vmax1, fmaxf(c[cg][q][2], c[cg][q][3]));
            }
        vmax0 = fmaxf(vmax0, __shfl_xor_sync(0xffffffffu, vmax0, 1));
        vmax0 = fmaxf(vmax0, __shfl_xor_sync(0xffffffffu, vmax0, 2));
        vmax1 = fmaxf(vmax1, __shfl_xor_sync(0xffffffffu, vmax1, 1));
        vmax1 = fmaxf(vmax1, __shfl_xor_sync(0xffffffffu, vmax1, 2));
        if (l4 == 0) {
            rmx[rg][g][lr] = vmax0;
            rmx[rg][g][lr + 8] = vmax1;
        }
        __syncthreads();
        float mx0 = fmaxf(rmx[rg][0][lr], rmx[rg][1][lr]);
        float mx1 = fmaxf(rmx[rg][0][lr + 8], rmx[rg][1][lr + 8]);

        const int r0 = t0 + rg * 16 + lr;
        __half* e0 = g_E + ((size_t)b * T_LEN + r0) * K2ST;
        __half* e1 = e0 + 8 * K2ST;
#pragma unroll
        for (int cg = 0; cg < 2; cg++)
#pragma unroll
            for (int q = 0; q < 8; q++) {
                int col = g * 64 + cg * 128 + q * 8 + l4 * 2;
                unsigned p0 = packh2(__expf(c[cg][q][0] - mx0), __expf(c[cg][q][1] - mx0));
                unsigned p1 = packh2(__expf(c[cg][q][2] - mx1), __expf(c[cg][q][3] - mx1));
                *reinterpret_cast<unsigned*>(e0 + col) = p0;
                *reinterpret_cast<unsigned*>(e1 + col) = p1;
            }
        if (g == 0 && l4 == 0) {
            if (r0 < len) msl += mx0;
            if (r0 + 8 < len) msl += mx1;
        }
    }

    // reduce masked m-sum across the block
    msl = warpSumf(msl);
    if (w < 4 && lane == 0) wsum[w] = msl;
    __syncthreads();
    if (tid == 0) g_msum[b] = (wsum[0] + wsum[1]) + (wsum[2] + wsum[3]);
}

// ---------------- K2: tensor-core forward recursion, ONE launch, warp per b ----------------
__global__ void __launch_bounds__(256) k2_fwd(const float* __restrict__ probs_w,
                                              const float* __restrict__ probs_x,
                                              const int* __restrict__ lengths,
                                              const int* __restrict__ mb) {
    const int wid = threadIdx.x >> 5, lane = threadIdx.x & 31;
    const int b = blockIdx.x * 8 + wid;
    const int len = __ldg(&lengths[__ldg(&mb[b])]);

    const int g = lane >> 2, t4 = lane & 3;
    unsigned Xf[4], Wf[4];
    Xf[0] = packh2(__ldg(&probs_x[(2 * t4) * 16 + g]),     __ldg(&probs_x[(2 * t4 + 1) * 16 + g]));
    Xf[1] = packh2(__ldg(&probs_x[(2 * t4 + 8) * 16 + g]), __ldg(&probs_x[(2 * t4 + 9) * 16 + g]));
    Xf[2] = packh2(__ldg(&probs_x[(2 * t4) * 16 + g + 8]),     __ldg(&probs_x[(2 * t4 + 1) * 16 + g + 8]));
    Xf[3] = packh2(__ldg(&probs_x[(2 * t4 + 8) * 16 + g + 8]), __ldg(&probs_x[(2 * t4 + 9) * 16 + g + 8]));
    Wf[0] = packh2(__ldg(&probs_w[(2 * t4) * 16 + g]),     __ldg(&probs_w[(2 * t4 + 1) * 16 + g]));
    Wf[1] = packh2(__ldg(&probs_w[(2 * t4 + 8) * 16 + g]), __ldg(&probs_w[(2 * t4 + 9) * 16 + g]));
    Wf[2] = packh2(__ldg(&probs_w[(2 * t4) * 16 + g + 8]),     __ldg(&probs_w[(2 * t4 + 1) * 16 + g + 8]));
    Wf[3] = packh2(__ldg(&probs_w[(2 * t4 + 8) * 16 + g + 8]), __ldg(&probs_w[(2 * t4 + 9) * 16 + g + 8]));

    const __half* eb = g_E + (size_t)b * T_LEN * K2ST;
    const int bn = 16 * g + 2 * t4;

    unsigned Z[4];
    float C;
    {
        float2 a0p = *reinterpret_cast<const float2*>(g_a0 + bn);
        float2 a1p = *reinterpret_cast<const float2*>(g_a0 + bn + 128);
        float2 a2p = *reinterpret_cast<const float2*>(g_a0 + bn + 8);
        float2 a3p = *reinterpret_cast<const float2*>(g_a0 + bn + 136);
        float2 e0p = __half22float2(*reinterpret_cast<const __half2*>(eb + bn));
        float2 e1p = __half22float2(*reinterpret_cast<const __half2*>(eb + bn + 128));
        float2 e2p = __half22float2(*reinterpret_cast<const __half2*>(eb + bn + 8));
        float2 e3p = __half22float2(*reinterpret_cast<const __half2*>(eb + bn + 136));
        float p0x = a0p.x * e0p.x, p0y = a0p.y * e0p.y;
        float p1x = a1p.x * e1p.x, p1y = a1p.y * e1p.y;
        float p2x = a2p.x * e2p.x, p2y = a2p.y * e2p.y;
        float p3x = a3p.x * e3p.x, p3y = a3p.y * e3p.y;
        float s0 = ((p0x + p0y) + (p1x + p1y)) + ((p2x + p2y) + (p3x + p3y));
        s0 = warpSumf(s0);
        float kap0 = __fdividef(1024.0f, s0);
        C = -__logf(kap0);
        Z[0] = packh2(p0x * kap0, p0y * kap0);
        Z[1] = packh2(p1x * kap0, p1y * kap0);
        Z[2] = packh2(p2x * kap0, p2y * kap0);
        Z[3] = packh2(p3x * kap0, p3y * kap0);
    }

    unsigned EA[4][4];
#pragma unroll
    for (int u = 0; u < 4; u++) {
        int tp = min(1 + u, len - 1);
        loadE4(EA[u], eb + (size_t)tp * K2ST, bn);
    }
    int t = 1;
    for (; t + 3 < len; t += 4) {
        stepZ(Z, C, EA[0], Xf, Wf);
        loadE4(EA[0], eb + (size_t)min(t + 4, len - 1) * K2ST, bn);
        stepZ(Z, C, EA[1], Xf, Wf);
        loadE4(EA[1], eb + (size_t)min(t + 5, len - 1) * K2ST, bn);
        stepZ(Z, C, EA[2], Xf, Wf);
        loadE4(EA[2], eb + (size_t)min(t + 6, len - 1) * K2ST, bn);
        stepZ(Z, C, EA[3], Xf, Wf);
        loadE4(EA[3], eb + (size_t)min(t + 7, len - 1) * K2ST, bn);
    }
    for (; t < len; t++) {
        unsigned E4[4];
        loadE4(E4, eb + (size_t)t * K2ST, bn);
        stepZ(Z, C, E4, Xf, Wf);
    }

    float2 f0 = __half22float2(u2h(Z[0]));
    float2 f1 = __half22float2(u2h(Z[1]));
    float2 f2 = __half22float2(u2h(Z[2]));
    float2 f3 = __half22float2(u2h(Z[3]));
    float s = ((f0.x + f0.y) + (f1.x + f1.y)) + ((f2.x + f2.y) + (f3.x + f3.y));
    s = warpSumf(s);
    C += __logf(s);
    if (lane == 0) g_C[b] = C;
}

// ---------------- K3: per-b loglik ----------------
__global__ void k3_loglik() {
    const int b = blockIdx.x * 256 + threadIdx.x;
    g_part[b] = g_C[b] + g_msum[b];
}

// ---------------- K4: final sum ----------------
__global__ void k4_sum(float* __restrict__ out) {
    __shared__ float red[8];
    const int lane = threadIdx.x & 31;
    const int w0 = threadIdx.x >> 5;
    float acc = 0.0f;
    for (int idx = threadIdx.x; idx < BATCH; idx += 256) acc += g_part[idx];
    acc = warpSumf(acc);
    if (lane == 0) red[w0] = acc;
    __syncthreads();
    if (threadIdx.x == 0) {
        float s = red[0];
#pragma unroll
        for (int w = 1; w < 8; w++) s += red[w];
        out[0] = s;
    }
}

// ---------------- launch ----------------
extern "C" void kernel_launch(void* const* d_in, const int* in_sizes, int n_in,
                              void* d_out, int out_size) {
    const float* seq     = (const float*)d_in[0];
    const float* probs_w = (const float*)d_in[1];
    const float* probs_x = (const float*)d_in[2];
    const float* w_init  = (const float*)d_in[3];
    const float* x_init  = (const float*)d_in[4];
    const float* probs_y = (const float*)d_in[5];
    const int*   lengths = (const int*)d_in[6];
    const int*   mb      = (const int*)d_in[7];
    float* out = (float*)d_out;

    cudaFuncSetAttribute(k1f_emis, cudaFuncAttributeMaxDynamicSharedMemorySize, SM_TOT);

    k0_setup<<<1, 256>>>(probs_y, w_init, x_init);
    k1f_emis<<<BATCH, 256, SM_TOT>>>(seq, lengths, mb);
    k2_fwd<<<BATCH / 8, 256>>>(probs_w, probs_x, lengths, mb);
    k3_loglik<<<BATCH / 256, 256>>>();
    k4_sum<<<1, 256>>>(out);
}

// round 9
// speedup vs baseline: 1.6774x; 1.0736x over previous
#include <cuda_runtime.h>
#include <cuda_fp16.h>
#include <cstdint>
#include <cstddef>

#define D_TONES 88
#define DPAD    104
#define T_LEN   512
#define K2ST    256
#define BATCH   1024
#define TILE_T  64
#define NTILES  8

// ---------------- device scratch ----------------
__device__ __align__(16) __half g_wdh[K2ST * DPAD];   // fp16 weights [k][d]
__device__ float g_cst[K2ST];                         // sum_d log1mp
__device__ float g_a0[K2ST];                          // linear init w_init*x_init
// E in k2-fragment-permuted layout: [b][t][lane][4 x half2] = 128 uint per (b,t)
__device__ __align__(16) unsigned g_Ep[(size_t)BATCH * T_LEN * 128];
__device__ float g_msum[BATCH];
__device__ float g_C[BATCH];
__device__ float g_part[BATCH];

// smem layout offsets for k1f (bytes)
#define SM_A    0                        // 64 x DPAD half  = 13312
#define SM_B    13312                    // 256 x DPAD half = 53248
#define SM_CST  66560                    // 256 f32 = 1024
#define SM_RMX  67584                    // 4 x 2 x 16 f32 = 512
#define SM_WSUM 68096                    // 8 f32 = 32
#define SM_STG  68128                    // 64 rows x 132 words x 4B = 33792
#define SM_TOT  101920

// ---------------- helpers ----------------
__device__ __forceinline__ unsigned smem_u32(const void* p) {
    return (unsigned)__cvta_generic_to_shared(p);
}
__device__ __forceinline__ float warpSumf(float v) {
#pragma unroll
    for (int s = 16; s > 0; s >>= 1) v += __shfl_xor_sync(0xffffffffu, v, s);
    return v;
}
__device__ __forceinline__ unsigned packh2(float lo, float hi) {
    __half2 h = __floats2half2_rn(lo, hi);
    return *reinterpret_cast<unsigned*>(&h);
}
__device__ __forceinline__ __half2 u2h(unsigned u) { return *reinterpret_cast<__half2*>(&u); }
__device__ __forceinline__ unsigned h2u(__half2 h) { return *reinterpret_cast<unsigned*>(&h); }
__device__ __forceinline__ unsigned movmT(unsigned s) {
    unsigned d;
    asm("movmatrix.sync.aligned.m8n8.trans.b16 %0,%1;" : "=r"(d) : "r"(s));
    return d;
}
__device__ __forceinline__ void mma16816(float d[4], const unsigned a[4],
                                         unsigned b0, unsigned b1) {
    asm volatile("mma.sync.aligned.m16n8k16.row.col.f32.f16.f16.f32 "
                 "{%0,%1,%2,%3},{%4,%5,%6,%7},{%8,%9},{%10,%11,%12,%13};"
                 : "=f"(d[0]), "=f"(d[1]), "=f"(d[2]), "=f"(d[3])
                 : "r"(a[0]), "r"(a[1]), "r"(a[2]), "r"(a[3]), "r"(b0), "r"(b1),
                   "f"(0.0f), "f"(0.0f), "f"(0.0f), "f"(0.0f));
}

// ---------------- K0: precompute ----------------
__global__ void k0_setup(const float* __restrict__ probs_y,
                         const float* __restrict__ w_init,
                         const float* __restrict__ x_init) {
    int k = threadIdx.x;  // 256
    float cs = 0.0f;
    for (int d = 0; d < DPAD; d++) {
        float w = 0.0f;
        if (d < D_TONES) {
            float py = probs_y[k * D_TONES + d];
            float l1 = log1pf(-py);
            w = logf(py) - l1;
            cs += l1;
        }
        g_wdh[k * DPAD + d] = __float2half_rn(w);
    }
    g_cst[k] = cs;
    g_a0[k] = w_init[k >> 4] * x_init[k & 15];
}

// ---------------- K1f: fused emission GEMM + rowmax + exp + permuted fp16 E ------------
__global__ void __launch_bounds__(256) k1f_emis(const float* __restrict__ seq,
                                                const int* __restrict__ lengths,
                                                const int* __restrict__ mb) {
    extern __shared__ __align__(16) unsigned char sraw[];
    __half (*Asm)[DPAD] = reinterpret_cast<__half(*)[DPAD]>(sraw + SM_A);
    __half (*Bsm)[DPAD] = reinterpret_cast<__half(*)[DPAD]>(sraw + SM_B);
    float* csm = reinterpret_cast<float*>(sraw + SM_CST);
    float (*rmx)[2][16] = reinterpret_cast<float(*)[2][16]>(sraw + SM_RMX);
    float* wsum = reinterpret_cast<float*>(sraw + SM_WSUM);
    unsigned* stg = reinterpret_cast<unsigned*>(sraw + SM_STG);   // [64][132] words

    const int b = blockIdx.x;
    const int tid = threadIdx.x;
    const int row = __ldg(&mb[b]);
    const int len = __ldg(&lengths[row]);

    // load all 256-state weights + cst into smem ONCE
    {
        const uint4* wp = reinterpret_cast<const uint4*>(g_wdh);
        uint4* bq = reinterpret_cast<uint4*>(&Bsm[0][0]);
        for (int idx = tid; idx < 256 * 13; idx += 256) bq[idx] = __ldg(&wp[idx]);
        csm[tid] = g_cst[tid];
        for (int r = tid; r < TILE_T; r += 256) {
            *reinterpret_cast<uint4*>(&Asm[r][88]) = make_uint4(0, 0, 0, 0);
            *reinterpret_cast<uint4*>(&Asm[r][96]) = make_uint4(0, 0, 0, 0);
        }
    }

    const int w = tid >> 5, lane = tid & 31;
    const int rg = w & 3;           // row group (16 rows)
    const int g  = w >> 2;          // col group (64-col slabs at g*64 and g*64+128)
    const int l4 = lane & 3, lr = lane >> 2;

    const unsigned aBase = smem_u32(&Asm[rg * 16 + (lane & 15)][(lane >> 4) * 8]);
    const unsigned bBase = smem_u32(&Bsm[g * 64 + ((lane >> 4) * 8) + (lane & 7)][((lane >> 3) & 1) * 8]);

    float msl = 0.0f;

    for (int tile = 0; tile < NTILES; tile++) {
        const int t0 = tile * TILE_T;
        if (t0 >= len) break;
        __syncthreads();   // staging reads done; (iter 0) B/cst/pad init complete

        // fill A tile (f32 -> fp16)
        const float4* sp = reinterpret_cast<const float4*>(
            seq + ((size_t)row * T_LEN + t0) * D_TONES);
        for (int idx = tid; idx < TILE_T * 22; idx += 256) {
            int r = idx / 22, c4 = idx % 22;
            float4 v = __ldg(&sp[(size_t)r * 22 + c4]);
            __half2 h0 = __floats2half2_rn(v.x, v.y);
            __half2 h1 = __floats2half2_rn(v.z, v.w);
            uint2 u;
            u.x = *reinterpret_cast<unsigned*>(&h0);
            u.y = *reinterpret_cast<unsigned*>(&h1);
            *reinterpret_cast<uint2*>(&Asm[r][c4 * 4]) = u;
        }
        __syncthreads();

        float c[2][8][4];
#pragma unroll
        for (int cg = 0; cg < 2; cg++)
#pragma unroll
            for (int q = 0; q < 8; q++) {
                c[cg][q][0] = 0.0f; c[cg][q][1] = 0.0f;
                c[cg][q][2] = 0.0f; c[cg][q][3] = 0.0f;
            }

#pragma unroll
        for (int ks = 0; ks < 6; ks++) {
            unsigned a0, a1, a2, a3;
            asm volatile("ldmatrix.sync.aligned.m8n8.x4.shared.b16 {%0,%1,%2,%3},[%4];"
                         : "=r"(a0), "=r"(a1), "=r"(a2), "=r"(a3) : "r"(aBase + ks * 32));
#pragma unroll
            for (int cg = 0; cg < 2; cg++) {
#pragma unroll
                for (int q16 = 0; q16 < 4; q16++) {
                    unsigned b0, b1, b2, b3;
                    asm volatile("ldmatrix.sync.aligned.m8n8.x4.shared.b16 {%0,%1,%2,%3},[%4];"
                                 : "=r"(b0), "=r"(b1), "=r"(b2), "=r"(b3)
                                 : "r"(bBase + (cg * 128 + q16 * 16) * (DPAD * 2) + ks * 32));
                    float* cl0 = c[cg][q16 * 2];
                    float* cl1 = c[cg][q16 * 2 + 1];
                    asm volatile("mma.sync.aligned.m16n8k16.row.col.f32.f16.f16.f32 "
                                 "{%0,%1,%2,%3},{%4,%5,%6,%7},{%8,%9},{%0,%1,%2,%3};"
                                 : "+f"(cl0[0]), "+f"(cl0[1]), "+f"(cl0[2]), "+f"(cl0[3])
                                 : "r"(a0), "r"(a1), "r"(a2), "r"(a3), "r"(b0), "r"(b1));
                    asm volatile("mma.sync.aligned.m16n8k16.row.col.f32.f16.f16.f32 "
                                 "{%0,%1,%2,%3},{%4,%5,%6,%7},{%8,%9},{%0,%1,%2,%3};"
                                 : "+f"(cl1[0]), "+f"(cl1[1]), "+f"(cl1[2]), "+f"(cl1[3])
                                 : "r"(a0), "r"(a1), "r"(a2), "r"(a3), "r"(b2), "r"(b3));
                }
            }
        }

        // epilogue: +cst, row max (quad + cross-warp via smem)
        float vmax0 = -3.4e38f, vmax1 = -3.4e38f;
#pragma unroll
        for (int cg = 0; cg < 2; cg++)
#pragma unroll
            for (int q = 0; q < 8; q++) {
                int col = g * 64 + cg * 128 + q * 8 + l4 * 2;
                float2 cst2 = *reinterpret_cast<const float2*>(&csm[col]);
                c[cg][q][0] += cst2.x; c[cg][q][1] += cst2.y;
                c[cg][q][2] += cst2.x; c[cg][q][3] += cst2.y;
                vmax0 = fmaxf(vmax0, fmaxf(c[cg][q][0], c[cg][q][1]));
                vmax1 = fmaxf(vmax1, fmaxf(c[cg][q][2], c[cg][q][3]));
            }
        vmax0 = fmaxf(vmax0, __shfl_xor_sync(0xffffffffu, vmax0, 1));
        vmax0 = fmaxf(vmax0, __shfl_xor_sync(0xffffffffu, vmax0, 2));
        vmax1 = fmaxf(vmax1, __shfl_xor_sync(0xffffffffu, vmax1, 1));
        vmax1 = fmaxf(vmax1, __shfl_xor_sync(0xffffffffu, vmax1, 2));
        if (l4 == 0) {
            rmx[rg][g][lr] = vmax0;
            rmx[rg][g][lr + 8] = vmax1;
        }
        __syncthreads();
        float mx0 = fmaxf(rmx[rg][0][lr], rmx[rg][1][lr]);
        float mx1 = fmaxf(rmx[rg][0][lr + 8], rmx[rg][1][lr + 8]);

        // exp -> staging (conflict-free: pad 132 words/row)
        const int r_lo = rg * 16 + lr;
#pragma unroll
        for (int cg = 0; cg < 2; cg++)
#pragma unroll
            for (int q = 0; q < 8; q++) {
                int wv = g * 32 + cg * 64 + q * 4 + l4;
                stg[r_lo * 132 + wv] =
                    packh2(__expf(c[cg][q][0] - mx0), __expf(c[cg][q][1] - mx0));
                stg[(r_lo + 8) * 132 + wv] =
                    packh2(__expf(c[cg][q][2] - mx1), __expf(c[cg][q][3] - mx1));
            }
        if (g == 0 && l4 == 0) {
            if (t0 + r_lo < len) msl += mx0;
            if (t0 + r_lo + 8 < len) msl += mx1;
        }
        __syncthreads();

        // permuted coalesced copy out: E'[b][t][lane] = uint4{bn, bn+128, bn+8, bn+136}
        uint4* eo = reinterpret_cast<uint4*>(g_Ep) + ((size_t)b * T_LEN + t0) * 32;
#pragma unroll
        for (int i = 0; i < 8; i++) {
            int item = tid + 256 * i;
            int t = item >> 5, ln = item & 31;
            int w0 = t * 132 + 8 * (ln >> 2) + (ln & 3);
            uint4 o;
            o.x = stg[w0];
            o.y = stg[w0 + 64];
            o.z = stg[w0 + 4];
            o.w = stg[w0 + 68];
            eo[item] = o;
        }
    }

    msl = warpSumf(msl);
    if (w < 4 && lane == 0) wsum[w] = msl;
    __syncthreads();
    if (tid == 0) g_msum[b] = (wsum[0] + wsum[1]) + (wsum[2] + wsum[3]);
}

// ---------------- K2: tensor-core recursion, warp per b, pipelined kappa, LDG.128 E ----
__global__ void __launch_bounds__(128) k2_fwd(const float* __restrict__ probs_w,
                                              const float* __restrict__ probs_x,
                                              const int* __restrict__ lengths,
                                              const int* __restrict__ mb) {
    const int wid = threadIdx.x >> 5, lane = threadIdx.x & 31;
    const int b = blockIdx.x * 4 + wid;
    const int len = __ldg(&lengths[__ldg(&mb[b])]);

    const int g = lane >> 2, t4 = lane & 3;
    unsigned Xf[4], Wf[4];
    Xf[0] = packh2(__ldg(&probs_x[(2 * t4) * 16 + g]),     __ldg(&probs_x[(2 * t4 + 1) * 16 + g]));
    Xf[1] = packh2(__ldg(&probs_x[(2 * t4 + 8) * 16 + g]), __ldg(&probs_x[(2 * t4 + 9) * 16 + g]));
    Xf[2] = packh2(__ldg(&probs_x[(2 * t4) * 16 + g + 8]),     __ldg(&probs_x[(2 * t4 + 1) * 16 + g + 8]));
    Xf[3] = packh2(__ldg(&probs_x[(2 * t4 + 8) * 16 + g + 8]), __ldg(&probs_x[(2 * t4 + 9) * 16 + g + 8]));
    Wf[0] = packh2(__ldg(&probs_w[(2 * t4) * 16 + g]),     __ldg(&probs_w[(2 * t4 + 1) * 16 + g]));
    Wf[1] = packh2(__ldg(&probs_w[(2 * t4 + 8) * 16 + g]), __ldg(&probs_w[(2 * t4 + 9) * 16 + g]));
    Wf[2] = packh2(__ldg(&probs_w[(2 * t4) * 16 + g + 8]),     __ldg(&probs_w[(2 * t4 + 1) * 16 + g + 8]));
    Wf[3] = packh2(__ldg(&probs_w[(2 * t4 + 8) * 16 + g + 8]), __ldg(&probs_w[(2 * t4 + 9) * 16 + g + 8]));

    const uint4* ep = reinterpret_cast<const uint4*>(g_Ep) + (size_t)b * T_LEN * 32 + lane;
    const int bn = 16 * g + 2 * t4;

    unsigned Z[4];
    float C;
    {
        uint4 e0 = ep[0];
        float2 a0p = *reinterpret_cast<const float2*>(g_a0 + bn);
        float2 a1p = *reinterpret_cast<const float2*>(g_a0 + bn + 128);
        float2 a2p = *reinterpret_cast<const float2*>(g_a0 + bn + 8);
        float2 a3p = *reinterpret_cast<const float2*>(g_a0 + bn + 136);
        float2 e0p = __half22float2(u2h(e0.x));
        float2 e1p = __half22float2(u2h(e0.y));
        float2 e2p = __half22float2(u2h(e0.z));
        float2 e3p = __half22float2(u2h(e0.w));
        float p0x = a0p.x * e0p.x, p0y = a0p.y * e0p.y;
        float p1x = a1p.x * e1p.x, p1y = a1p.y * e1p.y;
        float p2x = a2p.x * e2p.x, p2y = a2p.y * e2p.y;
        float p3x = a3p.x * e3p.x, p3y = a3p.y * e3p.y;
        float s0 = ((p0x + p0y) + (p1x + p1y)) + ((p2x + p2y) + (p3x + p3y));
        s0 = warpSumf(s0);
        float kap0 = __fdividef(1024.0f, s0);
        C = -__logf(kap0);
        Z[0] = packh2(p0x * kap0, p0y * kap0);
        Z[1] = packh2(p1x * kap0, p1y * kap0);
        Z[2] = packh2(p2x * kap0, p2y * kap0);
        Z[3] = packh2(p3x * kap0, p3y * kap0);
    }

    // kappa pipeline state: Z sums to exactly 1024 -> first applied kappa = 1
    __half2 kap2 = __half2half2(__float2half_rn(1.0f));
    float lk = 0.0f;

    uint4 EA[4];
#pragma unroll
    for (int u = 0; u < 4; u++) EA[u] = ep[(size_t)min(1 + u, len - 1) * 32];

    for (int t = 1; t < len; t++) {
        uint4 E = EA[0];
        EA[0] = EA[1]; EA[1] = EA[2]; EA[2] = EA[3];
        EA[3] = ep[(size_t)min(t + 4, len - 1) * 32];

        // sum of current Z (hadd2 tree + 5-shuffle butterfly, runs parallel to mma chain)
        __half2 hs = __hadd2(__hadd2(u2h(Z[0]), u2h(Z[1])), __hadd2(u2h(Z[2]), u2h(Z[3])));
        float2 fs = __half22float2(hs);
        float s = warpSumf(fs.x + fs.y);

        // apply pipelined kappa to E (off critical chain)
        __half2 ek0 = __hmul2(u2h(E.x), kap2);
        __half2 ek1 = __hmul2(u2h(E.y), kap2);
        __half2 ek2 = __hmul2(u2h(E.z), kap2);
        __half2 ek3 = __hmul2(u2h(E.w), kap2);
        C -= lk;

        // critical chain: U = Z*X ; T = U^T*W ; Z' = T^T ⊙ ek
        float U0[4], U1[4];
        mma16816(U0, Z, Xf[0], Xf[1]);
        mma16816(U1, Z, Xf[2], Xf[3]);
        unsigned Ut[4];
        Ut[0] = movmT(packh2(U0[0], U0[1]));
        Ut[1] = movmT(packh2(U1[0], U1[1]));
        Ut[2] = movmT(packh2(U0[2], U0[3]));
        Ut[3] = movmT(packh2(U1[2], U1[3]));
        float T0[4], T1[4];
        mma16816(T0, Ut, Wf[0], Wf[1]);
        mma16816(T1, Ut, Wf[2], Wf[3]);
        Z[0] = h2u(__hmul2(u2h(movmT(packh2(T0[0], T0[1]))), ek0));
        Z[1] = h2u(__hmul2(u2h(movmT(packh2(T1[0], T1[1]))), ek1));
        Z[2] = h2u(__hmul2(u2h(movmT(packh2(T0[2], T0[3]))), ek2));
        Z[3] = h2u(__hmul2(u2h(movmT(packh2(T1[2], T1[3]))), ek3));

        // finish kappa for next step
        float kap = fminf(__fdividef(1024.0f, s), 60000.0f);
        __half kh = __float2half_rn(kap);
        kap2 = __half2half2(kh);
        lk = __logf(__half2float(kh));
    }

    float2 f0 = __half22float2(u2h(Z[0]));
    float2 f1 = __half22float2(u2h(Z[1]));
    float2 f2 = __half22float2(u2h(Z[2]));
    float2 f3 = __half22float2(u2h(Z[3]));
    float s = ((f0.x + f0.y) + (f1.x + f1.y)) + ((f2.x + f2.y) + (f3.x + f3.y));
    s = warpSumf(s);
    C += __logf(s);
    if (lane == 0) g_C[b] = C;
}

// ---------------- K3: per-b loglik ----------------
__global__ void k3_loglik() {
    const int b = blockIdx.x * 256 + threadIdx.x;
    g_part[b] = g_C[b] + g_msum[b];
}

// ---------------- K4: final sum ----------------
__global__ void k4_sum(float* __restrict__ out) {
    __shared__ float red[8];
    const int lane = threadIdx.x & 31;
    const int w0 = threadIdx.x >> 5;
    float acc = 0.0f;
    for (int idx = threadIdx.x; idx < BATCH; idx += 256) acc += g_part[idx];
    acc = warpSumf(acc);
    if (lane == 0) red[w0] = acc;
    __syncthreads();
    if (threadIdx.x == 0) {
        float s = red[0];
#pragma unroll
        for (int w = 1; w < 8; w++) s += red[w];
        out[0] = s;
    }
}

// ---------------- launch ----------------
extern "C" void kernel_launch(void* const* d_in, const int* in_sizes, int n_in,
                              void* d_out, int out_size) {
    const float* seq     = (const float*)d_in[0];
    const float* probs_w = (const float*)d_in[1];
    const float* probs_x = (const float*)d_in[2];
    const float* w_init  = (const float*)d_in[3];
    const float* x_init  = (const float*)d_in[4];
    const float* probs_y = (const float*)d_in[5];
    const int*   lengths = (const int*)d_in[6];
    const int*   mb      = (const int*)d_in[7];
    float* out = (float*)d_out;

    cudaFuncSetAttribute(k1f_emis, cudaFuncAttributeMaxDynamicSharedMemorySize, SM_TOT);

    k0_setup<<<1, 256>>>(probs_y, w_init, x_init);
    k1f_emis<<<BATCH, 256, SM_TOT>>>(seq, lengths, mb);
    k2_fwd<<<BATCH / 4, 128>>>(probs_w, probs_x, lengths, mb);
    k3_loglik<<<BATCH / 256, 256>>>();
    k4_sum<<<1, 256>>>(out);
}

// round 10
// speedup vs baseline: 2.1708x; 1.2942x over previous
#include <cuda_runtime.h>
#include <cuda_fp16.h>
#include <cstdint>
#include <cstddef>

#define D_TONES 88
#define DPAD    104
#define T_LEN   512
#define K2ST    256
#define BATCH   1024
#define TILE_T  64
#define NTILES  8

// ---------------- device scratch ----------------
__device__ __align__(16) __half g_wdh[K2ST * DPAD];   // fp16 weights [k][d] (pad zeroed)
__device__ float g_cst[K2ST];                         // sum_d log1mp
__device__ float g_a0[K2ST];                          // linear init w_init*x_init
__device__ __align__(16) __half g_seqh[(size_t)BATCH * T_LEN * D_TONES]; // fp16 gathered seq
// E in k2-fragment-permuted layout: [b][t][lane][4 x half2]
__device__ __align__(16) unsigned g_Ep[(size_t)BATCH * T_LEN * 128];
__device__ float g_msum2[BATCH * 2];
__device__ float g_C[BATCH];

// smem layout offsets for k1f (bytes)
#define SM_B    0                        // 256 x 104 half = 53248
#define SM_A    53248                    // 2 x 64 x 104 half = 26624
#define SM_CST  79872                    // 256 f32 = 1024
#define SM_RMX  80896                    // 4 x 2 x 16 f32 = 512
#define SM_WSUM 81408                    // 8 f32 = 32
#define SM_STG  81440                    // 32 rows x 132 words x 4B = 16896
#define SM_TOT  98336

#define SWZ(wd) ((wd) ^ (((wd) >> 3) & 4))

// ---------------- helpers ----------------
__device__ __forceinline__ unsigned smem_u32(const void* p) {
    return (unsigned)__cvta_generic_to_shared(p);
}
#define CP_ASYNC16(dst, src) \
    asm volatile("cp.async.cg.shared.global [%0], [%1], 16;" :: "r"(dst), "l"(src))
#define CP_COMMIT() asm volatile("cp.async.commit_group;")
#define CP_WAIT1()  asm volatile("cp.async.wait_group 1;")

__device__ __forceinline__ float warpSumf(float v) {
#pragma unroll
    for (int s = 16; s > 0; s >>= 1) v += __shfl_xor_sync(0xffffffffu, v, s);
    return v;
}
__device__ __forceinline__ unsigned packh2(float lo, float hi) {
    __half2 h = __floats2half2_rn(lo, hi);
    return *reinterpret_cast<unsigned*>(&h);
}
__device__ __forceinline__ __half2 u2h(unsigned u) { return *reinterpret_cast<__half2*>(&u); }
__device__ __forceinline__ unsigned h2u(__half2 h) { return *reinterpret_cast<unsigned*>(&h); }
__device__ __forceinline__ unsigned movmT(unsigned s) {
    unsigned d;
    asm("movmatrix.sync.aligned.m8n8.trans.b16 %0,%1;" : "=r"(d) : "r"(s));
    return d;
}
__device__ __forceinline__ void mma16816(float d[4], const unsigned a[4],
                                         unsigned b0, unsigned b1) {
    asm volatile("mma.sync.aligned.m16n8k16.row.col.f32.f16.f16.f32 "
                 "{%0,%1,%2,%3},{%4,%5,%6,%7},{%8,%9},{%10,%11,%12,%13};"
                 : "=f"(d[0]), "=f"(d[1]), "=f"(d[2]), "=f"(d[3])
                 : "r"(a[0]), "r"(a[1]), "r"(a[2]), "r"(a[3]), "r"(b0), "r"(b1),
                   "f"(0.0f), "f"(0.0f), "f"(0.0f), "f"(0.0f));
}

// one recursion step: fp16 carry, one-step-lagged kappa folded into E (validated R9)
__device__ __forceinline__ void stepZ(unsigned Z[4], float& C, const uint4 E,
                                      const unsigned Xf[4], const unsigned Wf[4],
                                      __half2& kap2, float& lk) {
    __half2 hs = __hadd2(__hadd2(u2h(Z[0]), u2h(Z[1])), __hadd2(u2h(Z[2]), u2h(Z[3])));
    float2 fs = __half22float2(hs);
    float s = warpSumf(fs.x + fs.y);

    __half2 ek0 = __hmul2(u2h(E.x), kap2);
    __half2 ek1 = __hmul2(u2h(E.y), kap2);
    __half2 ek2 = __hmul2(u2h(E.z), kap2);
    __half2 ek3 = __hmul2(u2h(E.w), kap2);
    C -= lk;

    float U0[4], U1[4];
    mma16816(U0, Z, Xf[0], Xf[1]);
    mma16816(U1, Z, Xf[2], Xf[3]);
    unsigned Ut[4];
    Ut[0] = movmT(packh2(U0[0], U0[1]));
    Ut[1] = movmT(packh2(U1[0], U1[1]));
    Ut[2] = movmT(packh2(U0[2], U0[3]));
    Ut[3] = movmT(packh2(U1[2], U1[3]));
    float T0[4], T1[4];
    mma16816(T0, Ut, Wf[0], Wf[1]);
    mma16816(T1, Ut, Wf[2], Wf[3]);
    Z[0] = h2u(__hmul2(u2h(movmT(packh2(T0[0], T0[1]))), ek0));
    Z[1] = h2u(__hmul2(u2h(movmT(packh2(T1[0], T1[1]))), ek1));
    Z[2] = h2u(__hmul2(u2h(movmT(packh2(T0[2], T0[3]))), ek2));
    Z[3] = h2u(__hmul2(u2h(movmT(packh2(T1[2], T1[3]))), ek3));

    float kap = fminf(__fdividef(1024.0f, s), 60000.0f);
    __half kh = __float2half_rn(kap);
    kap2 = __half2half2(kh);
    lk = __logf(__half2float(kh));
}

// ---------------- K0: precompute (parallel: block per state k) ----------------
__global__ void __launch_bounds__(128) k0_setup(const float* __restrict__ probs_y,
                                                const float* __restrict__ w_init,
                                                const float* __restrict__ x_init) {
    __shared__ float red[4];
    const int k = blockIdx.x;
    const int d = threadIdx.x;
    float cs = 0.0f;
    if (d < D_TONES) {
        float py = __ldg(&probs_y[k * D_TONES + d]);
        float l1 = log1pf(-py);
        g_wdh[k * DPAD + d] = __float2half_rn(logf(py) - l1);
        cs = l1;
    } else if (d < DPAD) {
        g_wdh[k * DPAD + d] = __float2half_rn(0.0f);
    }
    cs = warpSumf(cs);
    if ((threadIdx.x & 31) == 0) red[threadIdx.x >> 5] = cs;
    __syncthreads();
    if (threadIdx.x == 0) {
        g_cst[k] = (red[0] + red[1]) + (red[2] + red[3]);
        g_a0[k] = __ldg(&w_init[k >> 4]) * __ldg(&x_init[k & 15]);
    }
}

// ---------------- K0b: gather mb rows, convert seq f32 -> fp16 ----------------
__global__ void __launch_bounds__(256) k0b_conv(const float* __restrict__ seq,
                                                const int* __restrict__ lengths,
                                                const int* __restrict__ mb) {
    const int b = blockIdx.x, seg = blockIdx.y;   // seg: 128 t-rows
    const int row = __ldg(&mb[b]);
    const int len = __ldg(&lengths[row]);
    if (seg * 128 >= len) return;
    const float4* src = reinterpret_cast<const float4*>(
        seq + ((size_t)row * T_LEN + seg * 128) * D_TONES);
    uint2* dst = reinterpret_cast<uint2*>(
        g_seqh + ((size_t)b * T_LEN + seg * 128) * D_TONES);
    for (int i = threadIdx.x; i < 128 * 22; i += 256) {
        float4 v = __ldg(&src[i]);
        dst[i] = make_uint2(h2u(__floats2half2_rn(v.x, v.y)),
                            h2u(__floats2half2_rn(v.z, v.w)));
    }
}

// ---------------- K1f: emission GEMM + rowmax + exp + permuted E, cp.async pipelined ----
__global__ void __launch_bounds__(256) k1f_emis(const int* __restrict__ lengths,
                                                const int* __restrict__ mb) {
    extern __shared__ __align__(16) unsigned char sraw[];
    __half (*Bsm)[DPAD] = reinterpret_cast<__half(*)[DPAD]>(sraw + SM_B);
    float* csm = reinterpret_cast<float*>(sraw + SM_CST);
    float (*rmx)[2][16] = reinterpret_cast<float(*)[2][16]>(sraw + SM_RMX);
    float* wsum = reinterpret_cast<float*>(sraw + SM_WSUM);
    unsigned* stg = reinterpret_cast<unsigned*>(sraw + SM_STG);   // [32][132] words

    const int b = blockIdx.x, halfb = blockIdx.y;   // halfb: tiles 0-3 / 4-7
    const int tid = threadIdx.x;
    const int len = __ldg(&lengths[__ldg(&mb[b])]);
    const int tstart = halfb * 4, tend = tstart + 4;
    if (tstart * TILE_T >= len) {
        if (tid == 0) g_msum2[b * 2 + halfb] = 0.0f;
        return;
    }

    const unsigned aBufBase = smem_u32(sraw + SM_A);
    const __half* seqb = g_seqh + (size_t)b * T_LEN * D_TONES;

    // prologue: prefetch A(tstart) into buf0
    {
        const char* src = reinterpret_cast<const char*>(seqb + (size_t)tstart * TILE_T * D_TONES);
        for (int cidx = tid; cidx < 704; cidx += 256) {
            int r = cidx / 11, o = cidx % 11;
            CP_ASYNC16(aBufBase + r * 208 + o * 16, src + r * 176 + o * 16);
        }
        CP_COMMIT();
    }
    // load B + cst; zero A pad cols (88..103) of both buffers
    {
        const uint4* wp = reinterpret_cast<const uint4*>(g_wdh);
        uint4* bq = reinterpret_cast<uint4*>(&Bsm[0][0]);
        for (int idx = tid; idx < 256 * 13; idx += 256) bq[idx] = __ldg(&wp[idx]);
        csm[tid] = g_cst[tid];
        for (int r = tid; r < 2 * TILE_T; r += 256) {
            char* base = reinterpret_cast<char*>(sraw) + SM_A + (r >> 6) * 13312 + (r & 63) * 208;
            *reinterpret_cast<uint4*>(base + 176) = make_uint4(0, 0, 0, 0);
            *reinterpret_cast<uint4*>(base + 192) = make_uint4(0, 0, 0, 0);
        }
    }

    const int w = tid >> 5, lane = tid & 31;
    const int rg = w & 3;           // row group (16 rows)
    const int g  = w >> 2;          // col group
    const int l4 = lane & 3, lr = lane >> 2;
    const unsigned aOff = (rg * 16 + (lane & 15)) * 208 + ((lane >> 4) * 8) * 2;
    const unsigned bBase = smem_u32(&Bsm[g * 64 + ((lane >> 4) * 8) + (lane & 7)][((lane >> 3) & 1) * 8]);

    float msl = 0.0f;
    int buf = 0;

    for (int tile = tstart; tile < tend; tile++) {
        const int t0 = tile * TILE_T;
        if (t0 >= len) break;

        // prefetch next tile's A into the other buffer (safe: last reader synced)
        if (tile + 1 < tend && (tile + 1) * TILE_T < len) {
            const char* src = reinterpret_cast<const char*>(
                seqb + (size_t)(tile + 1) * TILE_T * D_TONES);
            const unsigned dstb = aBufBase + (buf ^ 1) * 13312;
            for (int cidx = tid; cidx < 704; cidx += 256) {
                int r = cidx / 11, o = cidx % 11;
                CP_ASYNC16(dstb + r * 208 + o * 16, src + r * 176 + o * 16);
            }
        }
        CP_COMMIT();
        CP_WAIT1();
        __syncthreads();   // [S1] current A visible to all

        const unsigned aBase = aBufBase + buf * 13312 + aOff;

        float c[2][8][4];
#pragma unroll
        for (int cg = 0; cg < 2; cg++)
#pragma unroll
            for (int q = 0; q < 8; q++) {
                c[cg][q][0] = 0.0f; c[cg][q][1] = 0.0f;
                c[cg][q][2] = 0.0f; c[cg][q][3] = 0.0f;
            }

#pragma unroll
        for (int ks = 0; ks < 6; ks++) {
            unsigned a0, a1, a2, a3;
            asm volatile("ldmatrix.sync.aligned.m8n8.x4.shared.b16 {%0,%1,%2,%3},[%4];"
                         : "=r"(a0), "=r"(a1), "=r"(a2), "=r"(a3) : "r"(aBase + ks * 32));
#pragma unroll
            for (int cg = 0; cg < 2; cg++) {
#pragma unroll
                for (int q16 = 0; q16 < 4; q16++) {
                    unsigned b0, b1, b2, b3;
                    asm volatile("ldmatrix.sync.aligned.m8n8.x4.shared.b16 {%0,%1,%2,%3},[%4];"
                                 : "=r"(b0), "=r"(b1), "=r"(b2), "=r"(b3)
                                 : "r"(bBase + (cg * 128 + q16 * 16) * (DPAD * 2) + ks * 32));
                    float* cl0 = c[cg][q16 * 2];
                    float* cl1 = c[cg][q16 * 2 + 1];
                    asm volatile("mma.sync.aligned.m16n8k16.row.col.f32.f16.f16.f32 "
                                 "{%0,%1,%2,%3},{%4,%5,%6,%7},{%8,%9},{%0,%1,%2,%3};"
                                 : "+f"(cl0[0]), "+f"(cl0[1]), "+f"(cl0[2]), "+f"(cl0[3])
                                 : "r"(a0), "r"(a1), "r"(a2), "r"(a3), "r"(b0), "r"(b1));
                    asm volatile("mma.sync.aligned.m16n8k16.row.col.f32.f16.f16.f32 "
                                 "{%0,%1,%2,%3},{%4,%5,%6,%7},{%8,%9},{%0,%1,%2,%3};"
                                 : "+f"(cl1[0]), "+f"(cl1[1]), "+f"(cl1[2]), "+f"(cl1[3])
                                 : "r"(a0), "r"(a1), "r"(a2), "r"(a3), "r"(b2), "r"(b3));
                }
            }
        }

        // +cst, row max (quad + cross-warp via smem)
        float vmax0 = -3.4e38f, vmax1 = -3.4e38f;
#pragma unroll
        for (int cg = 0; cg < 2; cg++)
#pragma unroll
            for (int q = 0; q < 8; q++) {
                int col = g * 64 + cg * 128 + q * 8 + l4 * 2;
                float2 cst2 = *reinterpret_cast<const float2*>(&csm[col]);
                c[cg][q][0] += cst2.x; c[cg][q][1] += cst2.y;
                c[cg][q][2] += cst2.x; c[cg][q][3] += cst2.y;
                vmax0 = fmaxf(vmax0, fmaxf(c[cg][q][0], c[cg][q][1]));
                vmax1 = fmaxf(vmax1, fmaxf(c[cg][q][2], c[cg][q][3]));
            }
        vmax0 = fmaxf(vmax0, __shfl_xor_sync(0xffffffffu, vmax0, 1));
        vmax0 = fmaxf(vmax0, __shfl_xor_sync(0xffffffffu, vmax0, 2));
        vmax1 = fmaxf(vmax1, __shfl_xor_sync(0xffffffffu, vmax1, 1));
        vmax1 = fmaxf(vmax1, __shfl_xor_sync(0xffffffffu, vmax1, 2));
        if (l4 == 0) {
            rmx[rg][g][lr] = vmax0;
            rmx[rg][g][lr + 8] = vmax1;
        }
        __syncthreads();   // [S2]
        const float mx0 = fmaxf(rmx[rg][0][lr], rmx[rg][1][lr]);
        const float mx1 = fmaxf(rmx[rg][0][lr + 8], rmx[rg][1][lr + 8]);

        if (g == 0 && l4 == 0) {
            if (t0 + rg * 16 + lr < len) msl += mx0;
            if (t0 + rg * 16 + lr + 8 < len) msl += mx1;
        }

        // exp + pack into 32 unsigned (all threads, overlaps with phases)
        unsigned ue[2][8][2];
#pragma unroll
        for (int cg = 0; cg < 2; cg++)
#pragma unroll
            for (int q = 0; q < 8; q++) {
                ue[cg][q][0] = packh2(__expf(c[cg][q][0] - mx0), __expf(c[cg][q][1] - mx0));
                ue[cg][q][1] = packh2(__expf(c[cg][q][2] - mx1), __expf(c[cg][q][3] - mx1));
            }

        const int r0 = (rg & 1) * 16 + lr;   // staging row (0..31)
#pragma unroll
        for (int phase = 0; phase < 2; phase++) {
            if ((rg >> 1) == phase) {
#pragma unroll
                for (int cg = 0; cg < 2; cg++)
#pragma unroll
                    for (int q = 0; q < 8; q++) {
                        int wv = g * 32 + cg * 64 + q * 4 + l4;
                        stg[r0 * 132 + SWZ(wv)] = ue[cg][q][0];
                        stg[(r0 + 8) * 132 + SWZ(wv)] = ue[cg][q][1];
                    }
            }
            __syncthreads();   // staging ready
            uint4* eo = reinterpret_cast<uint4*>(g_Ep) +
                        ((size_t)b * T_LEN + t0 + 32 * phase) * 32;
#pragma unroll
            for (int i = 0; i < 4; i++) {
                int item = tid + 256 * i;
                int tl = item >> 5, ln = item & 31;
                int w0 = 8 * (ln >> 2) + (ln & 3);
                int base = tl * 132;
                uint4 o;
                o.x = stg[base + SWZ(w0)];
                o.y = stg[base + SWZ(w0 + 64)];
                o.z = stg[base + SWZ(w0 + 4)];
                o.w = stg[base + SWZ(w0 + 68)];
                eo[item] = o;
            }
            __syncthreads();   // staging consumed
        }
        buf ^= 1;
    }

    msl = warpSumf(msl);
    if (g == 0 && lane == 0) wsum[rg] = msl;
    __syncthreads();
    if (tid == 0)
        g_msum2[b * 2 + halfb] = (wsum[0] + wsum[1]) + (wsum[2] + wsum[3]);
}

// ---------------- K2: tensor-core recursion, warp per b, depth-8 prefetch --------------
__global__ void __launch_bounds__(128) k2_fwd(const float* __restrict__ probs_w,
                                              const float* __restrict__ probs_x,
                                              const int* __restrict__ lengths,
                                              const int* __restrict__ mb) {
    const int wid = threadIdx.x >> 5, lane = threadIdx.x & 31;
    const int b = blockIdx.x * 4 + wid;
    const int len = __ldg(&lengths[__ldg(&mb[b])]);

    const int g = lane >> 2, t4 = lane & 3;
    unsigned Xf[4], Wf[4];
    Xf[0] = packh2(__ldg(&probs_x[(2 * t4) * 16 + g]),     __ldg(&probs_x[(2 * t4 + 1) * 16 + g]));
    Xf[1] = packh2(__ldg(&probs_x[(2 * t4 + 8) * 16 + g]), __ldg(&probs_x[(2 * t4 + 9) * 16 + g]));
    Xf[2] = packh2(__ldg(&probs_x[(2 * t4) * 16 + g + 8]),     __ldg(&probs_x[(2 * t4 + 1) * 16 + g + 8]));
    Xf[3] = packh2(__ldg(&probs_x[(2 * t4 + 8) * 16 + g + 8]), __ldg(&probs_x[(2 * t4 + 9) * 16 + g + 8]));
    Wf[0] = packh2(__ldg(&probs_w[(2 * t4) * 16 + g]),     __ldg(&probs_w[(2 * t4 + 1) * 16 + g]));
    Wf[1] = packh2(__ldg(&probs_w[(2 * t4 + 8) * 16 + g]), __ldg(&probs_w[(2 * t4 + 9) * 16 + g]));
    Wf[2] = packh2(__ldg(&probs_w[(2 * t4) * 16 + g + 8]),     __ldg(&probs_w[(2 * t4 + 1) * 16 + g + 8]));
    Wf[3] = packh2(__ldg(&probs_w[(2 * t4 + 8) * 16 + g + 8]), __ldg(&probs_w[(2 * t4 + 9) * 16 + g + 8]));

    const uint4* ep = reinterpret_cast<const uint4*>(g_Ep) + (size_t)b * T_LEN * 32 + lane;
    const int bn = 16 * g + 2 * t4;

    unsigned Z[4];
    float C;
    {
        uint4 e0 = ep[0];
        float2 a0p = *reinterpret_cast<const float2*>(g_a0 + bn);
        float2 a1p = *reinterpret_cast<const float2*>(g_a0 + bn + 128);
        float2 a2p = *reinterpret_cast<const float2*>(g_a0 + bn + 8);
        float2 a3p = *reinterpret_cast<const float2*>(g_a0 + bn + 136);
        float2 e0p = __half22float2(u2h(e0.x));
        float2 e1p = __half22float2(u2h(e0.y));
        float2 e2p = __half22float2(u2h(e0.z));
        float2 e3p = __half22float2(u2h(e0.w));
        float p0x = a0p.x * e0p.x, p0y = a0p.y * e0p.y;
        float p1x = a1p.x * e1p.x, p1y = a1p.y * e1p.y;
        float p2x = a2p.x * e2p.x, p2y = a2p.y * e2p.y;
        float p3x = a3p.x * e3p.x, p3y = a3p.y * e3p.y;
        float s0 = ((p0x + p0y) + (p1x + p1y)) + ((p2x + p2y) + (p3x + p3y));
        s0 = warpSumf(s0);
        float kap0 = __fdividef(1024.0f, s0);
        C = -__logf(kap0);
        Z[0] = packh2(p0x * kap0, p0y * kap0);
        Z[1] = packh2(p1x * kap0, p1y * kap0);
        Z[2] = packh2(p2x * kap0, p2y * kap0);
        Z[3] = packh2(p3x * kap0, p3y * kap0);
    }

    __half2 kap2 = __half2half2(__float2half_rn(1.0f));
    float lk = 0.0f;

    uint4 EA[8];
#pragma unroll
    for (int u = 0; u < 8; u++) EA[u] = ep[(size_t)min(1 + u, len - 1) * 32];

    int t = 1;
    for (; t + 7 < len; t += 8) {
#pragma unroll
        for (int j = 0; j < 8; j++) {
            stepZ(Z, C, EA[j], Xf, Wf, kap2, lk);
            EA[j] = ep[(size_t)min(t + 8 + j, len - 1) * 32];
        }
    }
    for (int j = 0; t < len; t++, j++) stepZ(Z, C, EA[j], Xf, Wf, kap2, lk);

    float2 f0 = __half22float2(u2h(Z[0]));
    float2 f1 = __half22float2(u2h(Z[1]));
    float2 f2 = __half22float2(u2h(Z[2]));
    float2 f3 = __half22float2(u2h(Z[3]));
    float s = ((f0.x + f0.y) + (f1.x + f1.y)) + ((f2.x + f2.y) + (f3.x + f3.y));
    s = warpSumf(s);
    C += __logf(s);
    if (lane == 0) g_C[b] = C;
}

// ---------------- K4: final sum (loglik = C + msum halves) ----------------
__global__ void k4_sum(float* __restrict__ out) {
    __shared__ float red[8];
    const int lane = threadIdx.x & 31;
    const int w0 = threadIdx.x >> 5;
    float acc = 0.0f;
    for (int b = threadIdx.x; b < BATCH; b += 256)
        acc += g_C[b] + g_msum2[2 * b] + g_msum2[2 * b + 1];
    acc = warpSumf(acc);
    if (lane == 0) red[w0] = acc;
    __syncthreads();
    if (threadIdx.x == 0) {
        float s = red[0];
#pragma unroll
        for (int w = 1; w < 8; w++) s += red[w];
        out[0] = s;
    }
}

// ---------------- launch ----------------
extern "C" void kernel_launch(void* const* d_in, const int* in_sizes, int n_in,
                              void* d_out, int out_size) {
    const float* seq     = (const float*)d_in[0];
    const float* probs_w = (const float*)d_in[1];
    const float* probs_x = (const float*)d_in[2];
    const float* w_init  = (const float*)d_in[3];
    const float* x_init  = (const float*)d_in[4];
    const float* probs_y = (const float*)d_in[5];
    const int*   lengths = (const int*)d_in[6];
    const int*   mb      = (const int*)d_in[7];
    float* out = (float*)d_out;

    cudaFuncSetAttribute(k1f_emis, cudaFuncAttributeMaxDynamicSharedMemorySize, SM_TOT);

    k0_setup<<<K2ST, 128>>>(probs_y, w_init, x_init);
    k0b_conv<<<dim3(BATCH, 4), 256>>>(seq, lengths, mb);
    k1f_emis<<<dim3(BATCH, 2), 256, SM_TOT>>>(lengths, mb);
    k2_fwd<<<BATCH / 4, 128>>>(probs_w, probs_x, lengths, mb);
    k4_sum<<<1, 256>>>(out);
}

// round 11
// speedup vs baseline: 2.2095x; 1.0178x over previous
#include <cuda_runtime.h>
#include <cuda_fp16.h>
#include <cstdint>
#include <cstddef>

#define D_TONES 88
#define DPAD    104
#define T_LEN   512
#define K2ST    256
#define BATCH   1024
#define TILE_T  64
#define NTILES  8

// ---------------- device scratch ----------------
__device__ __align__(16) __half g_wdh[K2ST * DPAD];   // fp16 weights [k][d] (pad zeroed)
__device__ float g_cst[K2ST];                         // sum_d log1mp
__device__ float g_a0[K2ST];                          // linear init w_init*x_init
__device__ __align__(16) __half g_seqh[(size_t)BATCH * T_LEN * D_TONES]; // fp16 gathered seq
// E in k2-fragment-permuted layout: [b][t][lane][4 x half2]
__device__ __align__(16) unsigned g_Ep[(size_t)BATCH * T_LEN * 128];
__device__ float g_msum2[BATCH * 2];
__device__ float g_C[BATCH];

// smem layout offsets for k1f (bytes)
#define SM_B    0                        // 256 x 104 half = 53248
#define SM_A    53248                    // 2 x 64 x 104 half = 26624
#define SM_CST  79872                    // 256 f32 = 1024
#define SM_RMX  80896                    // 4 x 2 x 16 f32 = 512
#define SM_WSUM 81408                    // 8 f32 = 32
#define SM_STG  81440                    // 32 rows x 132 words x 4B = 16896
#define SM_TOT  98336

#define SWZ(wd) ((wd) ^ (((wd) >> 3) & 4))

// ---------------- helpers ----------------
__device__ __forceinline__ unsigned smem_u32(const void* p) {
    return (unsigned)__cvta_generic_to_shared(p);
}
#define CP_ASYNC16(dst, src) \
    asm volatile("cp.async.cg.shared.global [%0], [%1], 16;" :: "r"(dst), "l"(src))
#define CP_COMMIT() asm volatile("cp.async.commit_group;")
#define CP_WAIT1()  asm volatile("cp.async.wait_group 1;")

__device__ __forceinline__ float warpSumf(float v) {
#pragma unroll
    for (int s = 16; s > 0; s >>= 1) v += __shfl_xor_sync(0xffffffffu, v, s);
    return v;
}
// warp sum via integer redux (fixed point, scale 32) — ~80cy vs ~130cy butterfly.
// kappa derived from this is approximate but EXACTLY bookkept, so any value is correct.
__device__ __forceinline__ float warpSumRedux(float v) {
    unsigned pi = __float2uint_rn(fmaxf(v, 0.0f) * 32.0f);
    unsigned si;
    asm volatile("redux.sync.add.u32 %0, %1, 0xffffffff;" : "=r"(si) : "r"(pi));
    return __uint2float_rn(si) * 0.03125f;
}
__device__ __forceinline__ unsigned packh2(float lo, float hi) {
    __half2 h = __floats2half2_rn(lo, hi);
    return *reinterpret_cast<unsigned*>(&h);
}
__device__ __forceinline__ __half2 u2h(unsigned u) { return *reinterpret_cast<__half2*>(&u); }
__device__ __forceinline__ unsigned h2u(__half2 h) { return *reinterpret_cast<unsigned*>(&h); }
__device__ __forceinline__ unsigned movmT(unsigned s) {
    unsigned d;
    asm("movmatrix.sync.aligned.m8n8.trans.b16 %0,%1;" : "=r"(d) : "r"(s));
    return d;
}
__device__ __forceinline__ void mma16816(float d[4], const unsigned a[4],
                                         unsigned b0, unsigned b1) {
    asm volatile("mma.sync.aligned.m16n8k16.row.col.f32.f16.f16.f32 "
                 "{%0,%1,%2,%3},{%4,%5,%6,%7},{%8,%9},{%10,%11,%12,%13};"
                 : "=f"(d[0]), "=f"(d[1]), "=f"(d[2]), "=f"(d[3])
                 : "r"(a[0]), "r"(a[1]), "r"(a[2]), "r"(a[3]), "r"(b0), "r"(b1),
                   "f"(0.0f), "f"(0.0f), "f"(0.0f), "f"(0.0f));
}

// one recursion step: fp16 carry, one-step-lagged kappa folded into E.
// kappa sum uses int redux -> reduction chain (~80cy) now shorter than mma chain.
__device__ __forceinline__ void stepZ(unsigned Z[4], float& C, const uint4 E,
                                      const unsigned Xf[4], const unsigned Wf[4],
                                      __half2& kap2, float& lk) {
    __half2 hs = __hadd2(__hadd2(u2h(Z[0]), u2h(Z[1])), __hadd2(u2h(Z[2]), u2h(Z[3])));
    float2 fs = __half22float2(hs);
    float s = warpSumRedux(fs.x + fs.y);

    __half2 ek0 = __hmul2(u2h(E.x), kap2);
    __half2 ek1 = __hmul2(u2h(E.y), kap2);
    __half2 ek2 = __hmul2(u2h(E.z), kap2);
    __half2 ek3 = __hmul2(u2h(E.w), kap2);
    C -= lk;

    float U0[4], U1[4];
    mma16816(U0, Z, Xf[0], Xf[1]);
    mma16816(U1, Z, Xf[2], Xf[3]);
    unsigned Ut[4];
    Ut[0] = movmT(packh2(U0[0], U0[1]));
    Ut[1] = movmT(packh2(U1[0], U1[1]));
    Ut[2] = movmT(packh2(U0[2], U0[3]));
    Ut[3] = movmT(packh2(U1[2], U1[3]));
    float T0[4], T1[4];
    mma16816(T0, Ut, Wf[0], Wf[1]);
    mma16816(T1, Ut, Wf[2], Wf[3]);
    Z[0] = h2u(__hmul2(u2h(movmT(packh2(T0[0], T0[1]))), ek0));
    Z[1] = h2u(__hmul2(u2h(movmT(packh2(T1[0], T1[1]))), ek1));
    Z[2] = h2u(__hmul2(u2h(movmT(packh2(T0[2], T0[3]))), ek2));
    Z[3] = h2u(__hmul2(u2h(movmT(packh2(T1[2], T1[3]))), ek3));

    // kappa for NEXT step (off critical chain; guard s==0 -> clamp)
    float kap = fminf(__fdividef(1024.0f, fmaxf(s, 1e-30f)), 60000.0f);
    __half kh = __float2half_rn(kap);
    kap2 = __half2half2(kh);
    lk = __logf(__half2float(kh));
}

// ---------------- K0: precompute (parallel: block per state k) ----------------
__global__ void __launch_bounds__(128) k0_setup(const float* __restrict__ probs_y,
                                                const float* __restrict__ w_init,
                                                const float* __restrict__ x_init) {
    __shared__ float red[4];
    const int k = blockIdx.x;
    const int d = threadIdx.x;
    float cs = 0.0f;
    if (d < D_TONES) {
        float py = __ldg(&probs_y[k * D_TONES + d]);
        float l1 = log1pf(-py);
        g_wdh[k * DPAD + d] = __float2half_rn(logf(py) - l1);
        cs = l1;
    } else if (d < DPAD) {
        g_wdh[k * DPAD + d] = __float2half_rn(0.0f);
    }
    cs = warpSumf(cs);
    if ((threadIdx.x & 31) == 0) red[threadIdx.x >> 5] = cs;
    __syncthreads();
    if (threadIdx.x == 0) {
        g_cst[k] = (red[0] + red[1]) + (red[2] + red[3]);
        g_a0[k] = __ldg(&w_init[k >> 4]) * __ldg(&x_init[k & 15]);
    }
}

// ---------------- K0b: gather mb rows, convert seq f32 -> fp16 ----------------
__global__ void __launch_bounds__(256) k0b_conv(const float* __restrict__ seq,
                                                const int* __restrict__ lengths,
                                                const int* __restrict__ mb) {
    const int b = blockIdx.x, seg = blockIdx.y;   // seg: 128 t-rows
    const int row = __ldg(&mb[b]);
    const int len = __ldg(&lengths[row]);
    if (seg * 128 >= len) return;
    const float4* src = reinterpret_cast<const float4*>(
        seq + ((size_t)row * T_LEN + seg * 128) * D_TONES);
    uint2* dst = reinterpret_cast<uint2*>(
        g_seqh + ((size_t)b * T_LEN + seg * 128) * D_TONES);
    for (int i = threadIdx.x; i < 128 * 22; i += 256) {
        float4 v = __ldg(&src[i]);
        dst[i] = make_uint2(h2u(__floats2half2_rn(v.x, v.y)),
                            h2u(__floats2half2_rn(v.z, v.w)));
    }
}

// ---------------- K1f: emission GEMM + rowmax + exp + permuted E, cp.async pipelined ----
__global__ void __launch_bounds__(256) k1f_emis(const int* __restrict__ lengths,
                                                const int* __restrict__ mb) {
    extern __shared__ __align__(16) unsigned char sraw[];
    __half (*Bsm)[DPAD] = reinterpret_cast<__half(*)[DPAD]>(sraw + SM_B);
    float* csm = reinterpret_cast<float*>(sraw + SM_CST);
    float (*rmx)[2][16] = reinterpret_cast<float(*)[2][16]>(sraw + SM_RMX);
    float* wsum = reinterpret_cast<float*>(sraw + SM_WSUM);
    unsigned* stg = reinterpret_cast<unsigned*>(sraw + SM_STG);   // [32][132] words

    const int b = blockIdx.x, halfb = blockIdx.y;   // halfb: tiles 0-3 / 4-7
    const int tid = threadIdx.x;
    const int len = __ldg(&lengths[__ldg(&mb[b])]);
    const int tstart = halfb * 4, tend = tstart + 4;
    if (tstart * TILE_T >= len) {
        if (tid == 0) g_msum2[b * 2 + halfb] = 0.0f;
        return;
    }

    const unsigned aBufBase = smem_u32(sraw + SM_A);
    const __half* seqb = g_seqh + (size_t)b * T_LEN * D_TONES;

    // prologue: prefetch A(tstart) into buf0
    {
        const char* src = reinterpret_cast<const char*>(seqb + (size_t)tstart * TILE_T * D_TONES);
        for (int cidx = tid; cidx < 704; cidx += 256) {
            int r = cidx / 11, o = cidx % 11;
            CP_ASYNC16(aBufBase + r * 208 + o * 16, src + r * 176 + o * 16);
        }
        CP_COMMIT();
    }
    // load B + cst; zero A pad cols (88..103) of both buffers
    {
        const uint4* wp = reinterpret_cast<const uint4*>(g_wdh);
        uint4* bq = reinterpret_cast<uint4*>(&Bsm[0][0]);
        for (int idx = tid; idx < 256 * 13; idx += 256) bq[idx] = __ldg(&wp[idx]);
        csm[tid] = g_cst[tid];
        for (int r = tid; r < 2 * TILE_T; r += 256) {
            char* base = reinterpret_cast<char*>(sraw) + SM_A + (r >> 6) * 13312 + (r & 63) * 208;
            *reinterpret_cast<uint4*>(base + 176) = make_uint4(0, 0, 0, 0);
            *reinterpret_cast<uint4*>(base + 192) = make_uint4(0, 0, 0, 0);
        }
    }

    const int w = tid >> 5, lane = tid & 31;
    const int rg = w & 3;           // row group (16 rows)
    const int g  = w >> 2;          // col group
    const int l4 = lane & 3, lr = lane >> 2;
    const unsigned aOff = (rg * 16 + (lane & 15)) * 208 + ((lane >> 4) * 8) * 2;
    const unsigned bBase = smem_u32(&Bsm[g * 64 + ((lane >> 4) * 8) + (lane & 7)][((lane >> 3) & 1) * 8]);

    float msl = 0.0f;
    int buf = 0;

    for (int tile = tstart; tile < tend; tile++) {
        const int t0 = tile * TILE_T;
        if (t0 >= len) break;

        // prefetch next tile's A into the other buffer
        if (tile + 1 < tend && (tile + 1) * TILE_T < len) {
            const char* src = reinterpret_cast<const char*>(
                seqb + (size_t)(tile + 1) * TILE_T * D_TONES);
            const unsigned dstb = aBufBase + (buf ^ 1) * 13312;
            for (int cidx = tid; cidx < 704; cidx += 256) {
                int r = cidx / 11, o = cidx % 11;
                CP_ASYNC16(dstb + r * 208 + o * 16, src + r * 176 + o * 16);
            }
        }
        CP_COMMIT();
        CP_WAIT1();
        __syncthreads();   // [S1] current A visible to all

        const unsigned aBase = aBufBase + buf * 13312 + aOff;

        float c[2][8][4];
#pragma unroll
        for (int cg = 0; cg < 2; cg++)
#pragma unroll
            for (int q = 0; q < 8; q++) {
                c[cg][q][0] = 0.0f; c[cg][q][1] = 0.0f;
                c[cg][q][2] = 0.0f; c[cg][q][3] = 0.0f;
            }

#pragma unroll
        for (int ks = 0; ks < 6; ks++) {
            unsigned a0, a1, a2, a3;
            asm volatile("ldmatrix.sync.aligned.m8n8.x4.shared.b16 {%0,%1,%2,%3},[%4];"
                         : "=r"(a0), "=r"(a1), "=r"(a2), "=r"(a3) : "r"(aBase + ks * 32));
#pragma unroll
            for (int cg = 0; cg < 2; cg++) {
#pragma unroll
                for (int q16 = 0; q16 < 4; q16++) {
                    unsigned b0, b1, b2, b3;
                    asm volatile("ldmatrix.sync.aligned.m8n8.x4.shared.b16 {%0,%1,%2,%3},[%4];"
                                 : "=r"(b0), "=r"(b1), "=r"(b2), "=r"(b3)
                                 : "r"(bBase + (cg * 128 + q16 * 16) * (DPAD * 2) + ks * 32));
                    float* cl0 = c[cg][q16 * 2];
                    float* cl1 = c[cg][q16 * 2 + 1];
                    asm volatile("mma.sync.aligned.m16n8k16.row.col.f32.f16.f16.f32 "
                                 "{%0,%1,%2,%3},{%4,%5,%6,%7},{%8,%9},{%0,%1,%2,%3};"
                                 : "+f"(cl0[0]), "+f"(cl0[1]), "+f"(cl0[2]), "+f"(cl0[3])
                                 : "r"(a0), "r"(a1), "r"(a2), "r"(a3), "r"(b0), "r"(b1));
                    asm volatile("mma.sync.aligned.m16n8k16.row.col.f32.f16.f16.f32 "
                                 "{%0,%1,%2,%3},{%4,%5,%6,%7},{%8,%9},{%0,%1,%2,%3};"
                                 : "+f"(cl1[0]), "+f"(cl1[1]), "+f"(cl1[2]), "+f"(cl1[3])
                                 : "r"(a0), "r"(a1), "r"(a2), "r"(a3), "r"(b2), "r"(b3));
                }
            }
        }

        // +cst, row max (quad + cross-warp via smem)
        float vmax0 = -3.4e38f, vmax1 = -3.4e38f;
#pragma unroll
        for (int cg = 0; cg < 2; cg++)
#pragma unroll
            for (int q = 0; q < 8; q++) {
                int col = g * 64 + cg * 128 + q * 8 + l4 * 2;
                float2 cst2 = *reinterpret_cast<const float2*>(&csm[col]);
                c[cg][q][0] += cst2.x; c[cg][q][1] += cst2.y;
                c[cg][q][2] += cst2.x; c[cg][q][3] += cst2.y;
                vmax0 = fmaxf(vmax0, fmaxf(c[cg][q][0], c[cg][q][1]));
                vmax1 = fmaxf(vmax1, fmaxf(c[cg][q][2], c[cg][q][3]));
            }
        vmax0 = fmaxf(vmax0, __shfl_xor_sync(0xffffffffu, vmax0, 1));
        vmax0 = fmaxf(vmax0, __shfl_xor_sync(0xffffffffu, vmax0, 2));
        vmax1 = fmaxf(vmax1, __shfl_xor_sync(0xffffffffu, vmax1, 1));
        vmax1 = fmaxf(vmax1, __shfl_xor_sync(0xffffffffu, vmax1, 2));
        if (l4 == 0) {
            rmx[rg][g][lr] = vmax0;
            rmx[rg][g][lr + 8] = vmax1;
        }
        __syncthreads();   // [S2]
        const float mx0 = fmaxf(rmx[rg][0][lr], rmx[rg][1][lr]);
        const float mx1 = fmaxf(rmx[rg][0][lr + 8], rmx[rg][1][lr + 8]);

        if (g == 0 && l4 == 0) {
            if (t0 + rg * 16 + lr < len) msl += mx0;
            if (t0 + rg * 16 + lr + 8 < len) msl += mx1;
        }

        // exp + pack
        unsigned ue[2][8][2];
#pragma unroll
        for (int cg = 0; cg < 2; cg++)
#pragma unroll
            for (int q = 0; q < 8; q++) {
                ue[cg][q][0] = packh2(__expf(c[cg][q][0] - mx0), __expf(c[cg][q][1] - mx0));
                ue[cg][q][1] = packh2(__expf(c[cg][q][2] - mx1), __expf(c[cg][q][3] - mx1));
            }

        const int r0 = (rg & 1) * 16 + lr;   // staging row (0..31)
#pragma unroll
        for (int phase = 0; phase < 2; phase++) {
            if ((rg >> 1) == phase) {
#pragma unroll
                for (int cg = 0; cg < 2; cg++)
#pragma unroll
                    for (int q = 0; q < 8; q++) {
                        int wv = g * 32 + cg * 64 + q * 4 + l4;
                        stg[r0 * 132 + SWZ(wv)] = ue[cg][q][0];
                        stg[(r0 + 8) * 132 + SWZ(wv)] = ue[cg][q][1];
                    }
            }
            __syncthreads();   // staging ready
            uint4* eo = reinterpret_cast<uint4*>(g_Ep) +
                        ((size_t)b * T_LEN + t0 + 32 * phase) * 32;
#pragma unroll
            for (int i = 0; i < 4; i++) {
                int item = tid + 256 * i;
                int tl = item >> 5, ln = item & 31;
                int w0 = 8 * (ln >> 2) + (ln & 3);
                int base = tl * 132;
                uint4 o;
                o.x = stg[base + SWZ(w0)];
                o.y = stg[base + SWZ(w0 + 64)];
                o.z = stg[base + SWZ(w0 + 4)];
                o.w = stg[base + SWZ(w0 + 68)];
                eo[item] = o;
            }
            __syncthreads();   // staging consumed
        }
        buf ^= 1;
    }

    msl = warpSumf(msl);
    if (g == 0 && lane == 0) wsum[rg] = msl;
    __syncthreads();
    if (tid == 0)
        g_msum2[b * 2 + halfb] = (wsum[0] + wsum[1]) + (wsum[2] + wsum[3]);
}

// ---------------- K2: tensor-core recursion, warp per b, depth-8 prefetch --------------
__global__ void __launch_bounds__(128) k2_fwd(const float* __restrict__ probs_w,
                                              const float* __restrict__ probs_x,
                                              const int* __restrict__ lengths,
                                              const int* __restrict__ mb) {
    const int wid = threadIdx.x >> 5, lane = threadIdx.x & 31;
    const int b = blockIdx.x * 4 + wid;
    const int len = __ldg(&lengths[__ldg(&mb[b])]);

    const int g = lane >> 2, t4 = lane & 3;
    unsigned Xf[4], Wf[4];
    Xf[0] = packh2(__ldg(&probs_x[(2 * t4) * 16 + g]),     __ldg(&probs_x[(2 * t4 + 1) * 16 + g]));
    Xf[1] = packh2(__ldg(&probs_x[(2 * t4 + 8) * 16 + g]), __ldg(&probs_x[(2 * t4 + 9) * 16 + g]));
    Xf[2] = packh2(__ldg(&probs_x[(2 * t4) * 16 + g + 8]),     __ldg(&probs_x[(2 * t4 + 1) * 16 + g + 8]));
    Xf[3] = packh2(__ldg(&probs_x[(2 * t4 + 8) * 16 + g + 8]), __ldg(&probs_x[(2 * t4 + 9) * 16 + g + 8]));
    Wf[0] = packh2(__ldg(&probs_w[(2 * t4) * 16 + g]),     __ldg(&probs_w[(2 * t4 + 1) * 16 + g]));
    Wf[1] = packh2(__ldg(&probs_w[(2 * t4 + 8) * 16 + g]), __ldg(&probs_w[(2 * t4 + 9) * 16 + g]));
    Wf[2] = packh2(__ldg(&probs_w[(2 * t4) * 16 + g + 8]),     __ldg(&probs_w[(2 * t4 + 1) * 16 + g + 8]));
    Wf[3] = packh2(__ldg(&probs_w[(2 * t4 + 8) * 16 + g + 8]), __ldg(&probs_w[(2 * t4 + 9) * 16 + g + 8]));

    const uint4* ep = reinterpret_cast<const uint4*>(g_Ep) + (size_t)b * T_LEN * 32 + lane;
    const int bn = 16 * g + 2 * t4;

    unsigned Z[4];
    float C;
    {
        uint4 e0 = ep[0];
        float2 a0p = *reinterpret_cast<const float2*>(g_a0 + bn);
        float2 a1p = *reinterpret_cast<const float2*>(g_a0 + bn + 128);
        float2 a2p = *reinterpret_cast<const float2*>(g_a0 + bn + 8);
        float2 a3p = *reinterpret_cast<const float2*>(g_a0 + bn + 136);
        float2 e0p = __half22float2(u2h(e0.x));
        float2 e1p = __half22float2(u2h(e0.y));
        float2 e2p = __half22float2(u2h(e0.z));
        float2 e3p = __half22float2(u2h(e0.w));
        float p0x = a0p.x * e0p.x, p0y = a0p.y * e0p.y;
        float p1x = a1p.x * e1p.x, p1y = a1p.y * e1p.y;
        float p2x = a2p.x * e2p.x, p2y = a2p.y * e2p.y;
        float p3x = a3p.x * e3p.x, p3y = a3p.y * e3p.y;
        float s0 = ((p0x + p0y) + (p1x + p1y)) + ((p2x + p2y) + (p3x + p3y));
        s0 = warpSumf(s0);
        float kap0 = __fdividef(1024.0f, s0);
        C = -__logf(kap0);
        Z[0] = packh2(p0x * kap0, p0y * kap0);
        Z[1] = packh2(p1x * kap0, p1y * kap0);
        Z[2] = packh2(p2x * kap0, p2y * kap0);
        Z[3] = packh2(p3x * kap0, p3y * kap0);
    }

    __half2 kap2 = __half2half2(__float2half_rn(1.0f));
    float lk = 0.0f;

    uint4 EA[8];
#pragma unroll
    for (int u = 0; u < 8; u++) EA[u] = ep[(size_t)min(1 + u, len - 1) * 32];

    int t = 1;
    for (; t + 7 < len; t += 8) {
#pragma unroll
        for (int j = 0; j < 8; j++) {
            stepZ(Z, C, EA[j], Xf, Wf, kap2, lk);
            EA[j] = ep[(size_t)min(t + 8 + j, len - 1) * 32];
        }
    }
    for (int j = 0; t < len; t++, j++) stepZ(Z, C, EA[j], Xf, Wf, kap2, lk);

    float2 f0 = __half22float2(u2h(Z[0]));
    float2 f1 = __half22float2(u2h(Z[1]));
    float2 f2 = __half22float2(u2h(Z[2]));
    float2 f3 = __half22float2(u2h(Z[3]));
    float s = ((f0.x + f0.y) + (f1.x + f1.y)) + ((f2.x + f2.y) + (f3.x + f3.y));
    s = warpSumf(s);
    C += __logf(s);
    if (lane == 0) g_C[b] = C;
}

// ---------------- K4: final sum (loglik = C + msum halves) ----------------
__global__ void k4_sum(float* __restrict__ out) {
    __shared__ float red[8];
    const int lane = threadIdx.x & 31;
    const int w0 = threadIdx.x >> 5;
    float acc = 0.0f;
    for (int b = threadIdx.x; b < BATCH; b += 256)
        acc += g_C[b] + g_msum2[2 * b] + g_msum2[2 * b + 1];
    acc = warpSumf(acc);
    if (lane == 0) red[w0] = acc;
    __syncthreads();
    if (threadIdx.x == 0) {
        float s = red[0];
#pragma unroll
        for (int w = 1; w < 8; w++) s += red[w];
        out[0] = s;
    }
}

// ---------------- launch ----------------
extern "C" void kernel_launch(void* const* d_in, const int* in_sizes, int n_in,
                              void* d_out, int out_size) {
    const float* seq     = (const float*)d_in[0];
    const float* probs_w = (const float*)d_in[1];
    const float* probs_x = (const float*)d_in[2];
    const float* w_init  = (const float*)d_in[3];
    const float* x_init  = (const float*)d_in[4];
    const float* probs_y = (const float*)d_in[5];
    const int*   lengths = (const int*)d_in[6];
    const int*   mb      = (const int*)d_in[7];
    float* out = (float*)d_out;

    cudaFuncSetAttribute(k1f_emis, cudaFuncAttributeMaxDynamicSharedMemorySize, SM_TOT);

    k0_setup<<<K2ST, 128>>>(probs_y, w_init, x_init);
    k0b_conv<<<dim3(BATCH, 4), 256>>>(seq, lengths, mb);
    k1f_emis<<<dim3(BATCH, 2), 256, SM_TOT>>>(lengths, mb);
    k2_fwd<<<BATCH / 4, 128>>>(probs_w, probs_x, lengths, mb);
    k4_sum<<<1, 256>>>(out);
}